// round 6
// baseline (speedup 1.0000x reference)
#include <cuda_runtime.h>
#include <cstdint>
#include <math.h>

#define BATCH 8192
#define PLANE (8192 * 128)
#define GAIN 1.5927116870880127f
#define INV_SQRT3 0.57735026918962576f

// ---------------------------------------------------------------------------
// Scratch (device globals; no allocation in kernel_launch)
// ---------------------------------------------------------------------------
__device__ float g_s [PLANE];
__device__ float g_v [3 * PLANE];
__device__ float g_s1[PLANE];
__device__ float g_v1[3 * PLANE];
__device__ float g_s2[PLANE];
__device__ float g_v2[3 * PLANE];
__device__ float g_ts[PLANE];
__device__ float g_tv[3 * PLANE];
// packed bf16 hi/lo weights (prepass output)
__device__ uint32_t g_wp2[4u * 128 * 128 * 128];   // block2: 4 planes
__device__ uint32_t g_wp1[4u * 64 * 64 * 128];     // block1: 4 planes

// ---------------------------------------------------------------------------
// helpers (non-arch-gated PTX only: mma.sync bf16 m16n8k16 + cp.async, sm80+)
// ---------------------------------------------------------------------------
__device__ __forceinline__ uint32_t smem_u32(const void* p) {
    uint32_t a;
    asm("{ .reg .u64 t; cvta.to.shared.u64 t, %1; cvt.u32.u64 %0, t; }" : "=r"(a) : "l"(p));
    return a;
}
#define MMA_BF16(d, a0, a1, a2, a3, b0, b1)                                 \
    asm volatile(                                                           \
        "mma.sync.aligned.m16n8k16.row.col.f32.bf16.bf16.f32 "              \
        "{%0,%1,%2,%3}, {%4,%5,%6,%7}, {%8,%9}, {%0,%1,%2,%3};"             \
        : "+f"((d)[0]), "+f"((d)[1]), "+f"((d)[2]), "+f"((d)[3])            \
        : "r"(a0), "r"(a1), "r"(a2), "r"(a3), "r"(b0), "r"(b1))

#define CP_ASYNC16(sa, gp) \
    asm volatile("cp.async.ca.shared.global [%0], [%1], 16;" :: "r"(sa), "l"(gp) : "memory")
#define CP_COMMIT() asm volatile("cp.async.commit_group;" ::: "memory")
#define CP_WAIT1()  asm volatile("cp.async.wait_group 1;" ::: "memory")
#define CP_WAIT0()  asm volatile("cp.async.wait_group 0;" ::: "memory")

// split x0,x1 into packed bf16 hi word and lo (residual) word; low half = x0
__device__ __forceinline__ void split_pack(float x0, float x1,
                                           uint32_t& hi, uint32_t& lo) {
    uint32_t h;
    asm("cvt.rn.bf16x2.f32 %0, %1, %2;" : "=r"(h) : "f"(x1), "f"(x0));
    float h0 = __uint_as_float(h << 16);
    float h1 = __uint_as_float(h & 0xFFFF0000u);
    float l0 = x0 - h0;
    float l1 = x1 - h1;
    asm("cvt.rn.bf16x2.f32 %0, %1, %2;" : "=r"(lo) : "f"(l1), "f"(l0));
    hi = h;
}

// ---------------------------------------------------------------------------
// Weight prepass: fp32 w[u*M+v][n] -> packed hi/lo bf16x2 words, layout:
// block = vw*M + u (2048 words):
//   [hilo][kp 0..7][n' 0..127], n' = (n&7)*16 + (n>>3),
//   word = bf16(w[v=vw*16+2kp][n]) | bf16(w[v+1][n])<<16
// ---------------------------------------------------------------------------
__global__ void pack_weights_kernel(const float* __restrict__ w,
                                    uint32_t* __restrict__ dst, int M) {
    int idx = blockIdx.x * 256 + threadIdx.x;
    int total = (M * M / 2) * 128;
    if (idx >= total) return;
    int kpair = idx >> 7, n = idx & 127;
    int u = kpair / (M / 2), rem = kpair % (M / 2);
    int vw = rem >> 3, kp = rem & 7;
    int v = vw * 16 + 2 * kp;
    float x0 = w[((size_t)u * M + v) * 128 + n];
    float x1 = w[((size_t)u * M + v + 1) * 128 + n];
    uint32_t hi, lo;
    split_pack(x0, x1, hi, lo);
    int np = (n & 7) * 16 + (n >> 3);
    size_t base = ((size_t)(vw * M + u)) * 2048;
    dst[base + kp * 128 + np] = hi;
    dst[base + 1024 + kp * 128 + np] = lo;
}

// ---------------------------------------------------------------------------
// Tensor product via bf16x3 mma.sync, prepacked weights via cp.async.
// CTA: 64 batch rows x 128 w x 4 outputs; 16 warps = 4 outs x 4 row-quads.
// smem: bufw[2][8 part][8 kp][132] words (part = plane*2 + hilo).
// ---------------------------------------------------------------------------
template <int M>
__global__ __launch_bounds__(512, 1)
void tp_mma_kernel(const float* __restrict__ s1, const float* __restrict__ v1,
                   const float* __restrict__ s2, const float* __restrict__ v2,
                   const uint32_t* __restrict__ wp,   // 4 planes, stride M*M*128
                   float* __restrict__ ts, float* __restrict__ tv, float cscale) {
    extern __shared__ uint32_t dsm[];                 // 2 * 8448 words
    constexpr int PS = M * M * 128;                   // plane stride (words)
    const uint32_t smem_base = smem_u32(dsm);

    const int tid  = threadIdx.x;
    const int wid  = tid >> 5, lane = tid & 31;
    const int out  = wid & 3;
    const int q    = wid >> 2;
    const int g    = lane >> 2, t4 = lane & 3;
    const int bb   = blockIdx.x * 64;
    const int gb0  = bb + q * 16 + g;
    const int gb1  = gb0 + 8;

    // copy role
    const int cplane = tid >> 7;           // 0..3 weight plane
    const int crem   = tid & 127;
    const uint32_t* gw = wp + (size_t)cplane * PS;

    // part bases for this warp's two streams
    const int pa_hi = (out == 0) ? 0 : 4;  // ss / sv
    const int pb_hi = (out == 0) ? 2 : 6;  // vv / vs

    float acc[16][4];
#pragma unroll
    for (int nt = 0; nt < 16; ++nt)
#pragma unroll
        for (int j = 0; j < 4; ++j) acc[nt][j] = 0.f;

    const float* s1r0 = s1 + (size_t)gb0 * M;
    const float* s1r1 = s1 + (size_t)gb1 * M;
    const float* v1r0[3], *v1r1[3];
    const float* s2r0 = s2 + (size_t)gb0 * M;
    const float* s2r1 = s2 + (size_t)gb1 * M;
    const float* v2r0[3], *v2r1[3];
#pragma unroll
    for (int i = 0; i < 3; ++i) {
        v1r0[i] = v1 + (size_t)i * PLANE + (size_t)gb0 * M;
        v1r1[i] = v1 + (size_t)i * PLANE + (size_t)gb1 * M;
        v2r0[i] = v2 + (size_t)i * PLANE + (size_t)gb0 * M;
        v2r1[i] = v2 + (size_t)i * PLANE + (size_t)gb1 * M;
    }

    auto docopy = [&](int blk, int b) {
        const uint32_t* src = gw + (size_t)blk * 2048;
        const uint32_t sb0 = smem_base + (uint32_t)(b * 8448) * 4;
#pragma unroll
        for (int i = 0; i < 4; ++i) {
            int sg = crem + 128 * i;                      // 0..511
            int hilo = sg >> 8, kp = (sg >> 5) & 7, col = (sg & 31) * 4;
            uint32_t saddr = sb0 + (uint32_t)((((cplane * 2 + hilo) * 8 + kp) * 132 + col) * 4);
            CP_ASYNC16(saddr, src + (size_t)sg * 4);
        }
    };

    for (int vw = 0; vw < M / 16; ++vw) {
        const int v0w = vw * 16;
        const int blk0 = vw * M;

        docopy(blk0, 0);
        CP_COMMIT();

        for (int u = 0; u < M; ++u) {
            const int cur = u & 1;
            if (u + 1 < M) {
                docopy(blk0 + u + 1, cur ^ 1);
                CP_COMMIT();
                CP_WAIT1();
            } else {
                CP_WAIT0();
            }
            __syncthreads();

            // ---- a1, a2 operands (L1-resident gmem) ----
            float s1a[2], v1a[3][2];
            s1a[0] = __ldg(s1r0 + u);
            s1a[1] = __ldg(s1r1 + u);
#pragma unroll
            for (int i = 0; i < 3; ++i) {
                v1a[i][0] = __ldg(v1r0[i] + u);
                v1a[i][1] = __ldg(v1r1[i] + u);
            }
            const int ca = v0w + 2 * t4, cb = ca + 8;
            float s2v[2][4], v2v[3][2][4];
            {
                float2 A, B;
                A = __ldg((const float2*)(s2r0 + ca)); B = __ldg((const float2*)(s2r0 + cb));
                s2v[0][0]=A.x; s2v[0][1]=A.y; s2v[0][2]=B.x; s2v[0][3]=B.y;
                A = __ldg((const float2*)(s2r1 + ca)); B = __ldg((const float2*)(s2r1 + cb));
                s2v[1][0]=A.x; s2v[1][1]=A.y; s2v[1][2]=B.x; s2v[1][3]=B.y;
#pragma unroll
                for (int i = 0; i < 3; ++i) {
                    A = __ldg((const float2*)(v2r0[i] + ca)); B = __ldg((const float2*)(v2r0[i] + cb));
                    v2v[i][0][0]=A.x; v2v[i][0][1]=A.y; v2v[i][0][2]=B.x; v2v[i][0][3]=B.y;
                    A = __ldg((const float2*)(v2r1[i] + ca)); B = __ldg((const float2*)(v2r1[i] + cb));
                    v2v[i][1][0]=A.x; v2v[i][1][1]=A.y; v2v[i][1][2]=B.x; v2v[i][1][3]=B.y;
                }
            }

            // ---- products for both streams (a2 dead afterwards) ----
            float pav[2][4], pbv[2][4];
            if (out == 0) {
#pragma unroll
                for (int r = 0; r < 2; ++r)
#pragma unroll
                    for (int j = 0; j < 4; ++j) {
                        pav[r][j] = s1a[r] * s2v[r][j];
                        pbv[r][j] = INV_SQRT3 * (v1a[0][r] * v2v[0][r][j] +
                                                 v1a[1][r] * v2v[1][r][j] +
                                                 v1a[2][r] * v2v[2][r][j]);
                    }
            } else {
                const int i = out - 1;
#pragma unroll
                for (int r = 0; r < 2; ++r)
#pragma unroll
                    for (int j = 0; j < 4; ++j) {
                        pav[r][j] = s1a[r] * v2v[i][r][j];
                        pbv[r][j] = v1a[i][r] * s2v[r][j];
                    }
            }

            const uint32_t* bufb = dsm + cur * 8448;
            const uint32_t* bh0p = bufb + (pa_hi * 8 + t4) * 132 + g * 16;
            const uint32_t* bh1p = bufb + (pa_hi * 8 + t4 + 4) * 132 + g * 16;

            // ---- stream A: hi*hi + lo*hi + hi*lo ----
            {
                uint32_t fh[4], fl[4];
                split_pack(pav[0][0], pav[0][1], fh[0], fl[0]);
                split_pack(pav[1][0], pav[1][1], fh[1], fl[1]);
                split_pack(pav[0][2], pav[0][3], fh[2], fl[2]);
                split_pack(pav[1][2], pav[1][3], fh[3], fl[3]);
#pragma unroll
                for (int q4 = 0; q4 < 4; ++q4) {
                    uint4 h0 = *(const uint4*)(bh0p + q4 * 4);
                    uint4 h1 = *(const uint4*)(bh1p + q4 * 4);
                    uint4 l0 = *(const uint4*)(bh0p + 8 * 132 + q4 * 4);
                    uint4 l1 = *(const uint4*)(bh1p + 8 * 132 + q4 * 4);
                    uint32_t h0a[4] = {h0.x, h0.y, h0.z, h0.w};
                    uint32_t h1a[4] = {h1.x, h1.y, h1.z, h1.w};
                    uint32_t l0a[4] = {l0.x, l0.y, l0.z, l0.w};
                    uint32_t l1a[4] = {l1.x, l1.y, l1.z, l1.w};
#pragma unroll
                    for (int j = 0; j < 4; ++j) {
                        float* d = acc[q4 * 4 + j];
                        MMA_BF16(d, fh[0], fh[1], fh[2], fh[3], h0a[j], h1a[j]);
                        MMA_BF16(d, fl[0], fl[1], fl[2], fl[3], h0a[j], h1a[j]);
                        MMA_BF16(d, fh[0], fh[1], fh[2], fh[3], l0a[j], l1a[j]);
                    }
                }
            }
            // ---- stream B ----
            {
                const uint32_t* ch0p = bufb + (pb_hi * 8 + t4) * 132 + g * 16;
                const uint32_t* ch1p = bufb + (pb_hi * 8 + t4 + 4) * 132 + g * 16;
                uint32_t fh[4], fl[4];
                split_pack(pbv[0][0], pbv[0][1], fh[0], fl[0]);
                split_pack(pbv[1][0], pbv[1][1], fh[1], fl[1]);
                split_pack(pbv[0][2], pbv[0][3], fh[2], fl[2]);
                split_pack(pbv[1][2], pbv[1][3], fh[3], fl[3]);
#pragma unroll
                for (int q4 = 0; q4 < 4; ++q4) {
                    uint4 h0 = *(const uint4*)(ch0p + q4 * 4);
                    uint4 h1 = *(const uint4*)(ch1p + q4 * 4);
                    uint4 l0 = *(const uint4*)(ch0p + 8 * 132 + q4 * 4);
                    uint4 l1 = *(const uint4*)(ch1p + 8 * 132 + q4 * 4);
                    uint32_t h0a[4] = {h0.x, h0.y, h0.z, h0.w};
                    uint32_t h1a[4] = {h1.x, h1.y, h1.z, h1.w};
                    uint32_t l0a[4] = {l0.x, l0.y, l0.z, l0.w};
                    uint32_t l1a[4] = {l1.x, l1.y, l1.z, l1.w};
#pragma unroll
                    for (int j = 0; j < 4; ++j) {
                        float* d = acc[q4 * 4 + j];
                        MMA_BF16(d, fh[0], fh[1], fh[2], fh[3], h0a[j], h1a[j]);
                        MMA_BF16(d, fl[0], fl[1], fl[2], fl[3], h0a[j], h1a[j]);
                        MMA_BF16(d, fh[0], fh[1], fh[2], fh[3], l0a[j], l1a[j]);
                    }
                }
            }
            __syncthreads();   // consumers done before next overwrite
        }
    }

    // epilogue: n = nt*8 + g, thread cols 2*t4, 2*t4+1 within n-tile
    float* op = (out == 0) ? ts : tv + (size_t)(out - 1) * PLANE;
#pragma unroll
    for (int nt = 0; nt < 16; ++nt) {
        const int col = nt * 8 + 2 * t4;
        *(float2*)(op + (size_t)gb0 * 128 + col) =
            make_float2(cscale * acc[nt][0], cscale * acc[nt][1]);
        *(float2*)(op + (size_t)gb1 * 128 + col) =
            make_float2(cscale * acc[nt][2], cscale * acc[nt][3]);
    }
}

// ---------------------------------------------------------------------------
// split / pack / gemm / gate
// ---------------------------------------------------------------------------
__global__ void split_kernel(const float* __restrict__ x,
                             float* __restrict__ s, float* __restrict__ v) {
    int i = blockIdx.x * 256 + threadIdx.x;
    if (i >= BATCH * 64) return;
    int b = i >> 6, u = i & 63;
    const float* xr = x + b * 256;
    s[i] = xr[u];
    v[0 * PLANE + i] = xr[64 + 3 * u + 0];
    v[1 * PLANE + i] = xr[64 + 3 * u + 1];
    v[2 * PLANE + i] = xr[64 + 3 * u + 2];
}

__global__ void pack_kernel(const float* __restrict__ s,
                            const float* __restrict__ v,
                            float* __restrict__ out) {
    int i = blockIdx.x * 256 + threadIdx.x;
    if (i >= BATCH * 64) return;
    int b = i >> 6, u = i & 63;
    float* orow = out + b * 256;
    orow[u] = s[i];
    orow[64 + 3 * u + 0] = v[0 * PLANE + i];
    orow[64 + 3 * u + 1] = v[1 * PLANE + i];
    orow[64 + 3 * u + 2] = v[2 * PLANE + i];
}

// 32-row tiles for occupancy (grid = 256 * planes)
template <int NC>
__global__ __launch_bounds__(256)
void gemm_kernel(const float* __restrict__ X, const float* __restrict__ Wm,
                 float* __restrict__ Y, int K, float scale) {
    constexpr int N = 32 * NC;
    X += (size_t)blockIdx.y * PLANE;
    Y += (size_t)blockIdx.y * PLANE;
    __shared__ float Xs[32][33];
    __shared__ float Ws[32][N + 1];
    const int tx = threadIdx.x, ty = threadIdx.y;
    const int tid = ty * 32 + tx;
    const int row0 = blockIdx.x * 32;

    float acc[4][NC];
#pragma unroll
    for (int r = 0; r < 4; ++r)
#pragma unroll
        for (int j = 0; j < NC; ++j) acc[r][j] = 0.f;

    for (int k0 = 0; k0 < K; k0 += 32) {
#pragma unroll
        for (int e = tid; e < 32 * 32; e += 256) {
            int r = e >> 5, kk = e & 31;
            Xs[r][kk] = X[(size_t)(row0 + r) * K + k0 + kk];
        }
        for (int e = tid; e < 32 * N; e += 256) {
            int kk = e / N, n = e - kk * N;
            Ws[kk][n] = Wm[(size_t)(k0 + kk) * N + n];
        }
        __syncthreads();
#pragma unroll 8
        for (int kk = 0; kk < 32; ++kk) {
            float wv[NC];
#pragma unroll
            for (int j = 0; j < NC; ++j) wv[j] = Ws[kk][tx * NC + j];
#pragma unroll
            for (int r = 0; r < 4; ++r) {
                float xv = Xs[ty * 4 + r][kk];
#pragma unroll
                for (int j = 0; j < NC; ++j) acc[r][j] += xv * wv[j];
            }
        }
        __syncthreads();
    }
#pragma unroll
    for (int r = 0; r < 4; ++r)
#pragma unroll
        for (int j = 0; j < NC; ++j)
            Y[(size_t)(row0 + ty * 4 + r) * N + tx * NC + j] = scale * acc[r][j];
}

__global__ void gate_kernel(const float* __restrict__ sl, const float* __restrict__ g,
                            const float* __restrict__ vl,
                            float* __restrict__ gs, float* __restrict__ gv) {
    int i = blockIdx.x * 256 + threadIdx.x;
    if (i >= BATCH * 128) return;
    gs[i] = GAIN * tanhf(sl[i]);
    float t = GAIN * tanhf(g[i]);
    gv[0 * PLANE + i] = t * vl[0 * PLANE + i];
    gv[1 * PLANE + i] = t * vl[1 * PLANE + i];
    gv[2 * PLANE + i] = t * vl[2 * PLANE + i];
}

// ---------------------------------------------------------------------------
// Host orchestration
// ---------------------------------------------------------------------------
static inline void run_gemm(const float* X, const float* W, float* Y,
                            int K, int N, float scale, int planes) {
    dim3 blk(32, 8), grd(BATCH / 32, planes);
    if (N == 64) gemm_kernel<2><<<grd, blk>>>(X, W, Y, K, scale);
    else         gemm_kernel<4><<<grd, blk>>>(X, W, Y, K, scale);
}

extern "C" void kernel_launch(void* const* d_in, const int* in_sizes, int n_in,
                              void* d_out, int out_size) {
    const float* in[29];
    for (int i = 0; i < 29; ++i) in[i] = (const float*)d_in[i];
    float* out = (float*)d_out;

    float *s, *v, *s1, *v1, *s2, *v2, *ts, *tv;
    uint32_t *wp1, *wp2;
    cudaGetSymbolAddress((void**)&s,  g_s);
    cudaGetSymbolAddress((void**)&v,  g_v);
    cudaGetSymbolAddress((void**)&s1, g_s1);
    cudaGetSymbolAddress((void**)&v1, g_v1);
    cudaGetSymbolAddress((void**)&s2, g_s2);
    cudaGetSymbolAddress((void**)&v2, g_v2);
    cudaGetSymbolAddress((void**)&ts, g_ts);
    cudaGetSymbolAddress((void**)&tv, g_tv);
    cudaGetSymbolAddress((void**)&wp1, g_wp1);
    cudaGetSymbolAddress((void**)&wp2, g_wp2);

    const int TP_SMEM = 2 * 8448 * 4;   // 67584 bytes
    cudaFuncSetAttribute(tp_mma_kernel<64>,
                         cudaFuncAttributeMaxDynamicSharedMemorySize, TP_SMEM);
    cudaFuncSetAttribute(tp_mma_kernel<128>,
                         cudaFuncAttributeMaxDynamicSharedMemorySize, TP_SMEM);

    const float c64  = 0.125f;
    const float c128 = 0.08838834764831845f;
    const float ctp1 = 1.0f / (64.0f  * 1.4142135623730951f);
    const float ctp2 = 1.0f / (128.0f * 1.4142135623730951f);

    // ---- weight prepass (deterministic, every call) ----
    {
        const int t1 = (64 * 64 / 2) * 128;     // per block1 plane
        const int t2 = (128 * 128 / 2) * 128;   // per block2 plane
        for (int p = 0; p < 4; ++p)
            pack_weights_kernel<<<(t1 + 255) / 256, 256>>>(in[5 + p],  wp1 + (size_t)p * (64 * 64 * 128), 64);
        for (int p = 0; p < 4; ++p)
            pack_weights_kernel<<<(t2 + 255) / 256, 256>>>(in[18 + p], wp2 + (size_t)p * (128 * 128 * 128), 128);
    }

    split_kernel<<<BATCH * 64 / 256, 256>>>(in[0], s, v);

    // ---------------- block 1 (m = 64) ----------------
    run_gemm(s, in[1], s1, 64, 64, c64, 1);
    run_gemm(v, in[2], v1, 64, 64, c64, 3);
    run_gemm(s, in[3], s2, 64, 64, c64, 1);
    run_gemm(v, in[4], v2, 64, 64, c64, 3);

    tp_mma_kernel<64><<<BATCH / 64, 512, TP_SMEM>>>(
        s1, v1, s2, v2, wp1, ts, tv, ctp1);

    run_gemm(ts, in[9],  s1, 128, 128, c128, 1);
    run_gemm(ts, in[10], s2, 128, 128, c128, 1);
    run_gemm(tv, in[11], v1, 128, 128, c128, 3);
    gate_kernel<<<BATCH * 128 / 256, 256>>>(s1, s2, v1, ts, tv);

    run_gemm(ts, in[12], s, 128, 128, c128, 1);
    run_gemm(tv, in[13], v, 128, 128, c128, 3);

    // ---------------- block 2 (m = 128) ----------------
    run_gemm(s, in[14], s1, 128, 128, c128, 1);
    run_gemm(v, in[15], v1, 128, 128, c128, 3);
    run_gemm(s, in[16], s2, 128, 128, c128, 1);
    run_gemm(v, in[17], v2, 128, 128, c128, 3);

    tp_mma_kernel<128><<<BATCH / 64, 512, TP_SMEM>>>(
        s1, v1, s2, v2, wp2, ts, tv, ctp2);

    run_gemm(ts, in[22], s1, 128, 128, c128, 1);
    run_gemm(ts, in[23], s2, 128, 128, c128, 1);
    run_gemm(tv, in[24], v1, 128, 128, c128, 3);
    gate_kernel<<<BATCH * 128 / 256, 256>>>(s1, s2, v1, ts, tv);

    run_gemm(ts, in[25], s, 128, 128, c128, 1);
    run_gemm(tv, in[26], v, 128, 128, c128, 3);

    // ---------------- final linear + pack ----------------
    run_gemm(s, in[27], s1, 128, 64, c128, 1);
    run_gemm(v, in[28], v1, 128, 64, c128, 3);

    pack_kernel<<<BATCH * 64 / 256, 256>>>(s1, v1, out);
}

// round 7
// speedup vs baseline: 1.4563x; 1.4563x over previous
#include <cuda_runtime.h>
#include <cstdint>
#include <math.h>

#define BATCH 8192
#define PLANE (8192 * 128)
#define GAIN 1.5927116870880127f
#define INV_SQRT3 0.57735026918962576f

__device__ float g_s [PLANE];
__device__ float g_v [3 * PLANE];
__device__ float g_s1[PLANE];
__device__ float g_v1[3 * PLANE];
__device__ float g_s2[PLANE];
__device__ float g_v2[3 * PLANE];
__device__ float g_ts[PLANE];
__device__ float g_tv[3 * PLANE];
__device__ uint32_t g_wp1[2u * 64 * 64 * 128];      // P-form ss,vv block1
__device__ uint32_t g_wp2[2u * 128 * 128 * 128];    // P-form ss,vv block2
__device__ uint32_t g_wv1[2u * 64 * 64 * 128];      // V-form sv,vs block1
__device__ uint32_t g_wv2[2u * 128 * 128 * 128];    // V-form sv,vs block2

__device__ __forceinline__ uint32_t smem_u32(const void* p) {
    uint32_t a;
    asm("{ .reg .u64 t; cvta.to.shared.u64 t, %1; cvt.u32.u64 %0, t; }" : "=r"(a) : "l"(p));
    return a;
}
#define MMA_BF16(d, a0, a1, a2, a3, b0, b1)                                 \
    asm volatile(                                                           \
        "mma.sync.aligned.m16n8k16.row.col.f32.bf16.bf16.f32 "              \
        "{%0,%1,%2,%3}, {%4,%5,%6,%7}, {%8,%9}, {%0,%1,%2,%3};"             \
        : "+f"((d)[0]), "+f"((d)[1]), "+f"((d)[2]), "+f"((d)[3])            \
        : "r"(a0), "r"(a1), "r"(a2), "r"(a3), "r"(b0), "r"(b1))
#define CP_ASYNC16(sa, gp) \
    asm volatile("cp.async.ca.shared.global [%0], [%1], 16;" :: "r"(sa), "l"(gp) : "memory")
#define CP_COMMIT() asm volatile("cp.async.commit_group;" ::: "memory")
#define CP_WAIT1()  asm volatile("cp.async.wait_group 1;" ::: "memory")
#define CP_WAIT0()  asm volatile("cp.async.wait_group 0;" ::: "memory")

__device__ __forceinline__ void split_pack(float x0, float x1,
                                           uint32_t& hi, uint32_t& lo) {
    uint32_t h;
    asm("cvt.rn.bf16x2.f32 %0, %1, %2;" : "=r"(h) : "f"(x1), "f"(x0));
    float l0 = x0 - __uint_as_float(h << 16);
    float l1 = x1 - __uint_as_float(h & 0xFFFF0000u);
    asm("cvt.rn.bf16x2.f32 %0, %1, %2;" : "=r"(lo) : "f"(l1), "f"(l0));
    hi = h;
}

// P-form prepass: block (vw*M+u): [hilo][kp][n'], n'=(n&7)*16+(n>>3)
__global__ void pack_weights_kernel(const float* __restrict__ w,
                                    uint32_t* __restrict__ dst, int M) {
    int idx = blockIdx.x * 256 + threadIdx.x;
    if (idx >= (M * M / 2) * 128) return;
    int kpair = idx >> 7, n = idx & 127;
    int u = kpair / (M / 2), rem = kpair % (M / 2);
    int vw = rem >> 3, kp = rem & 7;
    int v = vw * 16 + 2 * kp;
    uint32_t hi, lo;
    split_pack(w[((size_t)u * M + v) * 128 + n], w[((size_t)u * M + v + 1) * 128 + n], hi, lo);
    int np = (n & 7) * 16 + (n >> 3);
    size_t base = ((size_t)(vw * M + u)) * 2048;
    dst[base + kp * 128 + np] = hi;
    dst[base + 1024 + kp * 128 + np] = lo;
}

// V-form prepass: chunk ci=m*NCHK+kh: [ci][hilo][kp 0..15][n']; k = kh*32+2kp
__global__ void pack_weights_v_kernel(const float* __restrict__ w,
                                      uint32_t* __restrict__ dst, int M, int transpose) {
    int idx = blockIdx.x * 256 + threadIdx.x;
    if (idx >= (M * M / 2) * 128) return;
    int gkp = idx >> 7, n = idx & 127;
    int m = gkp / (M / 2), kp_g = gkp % (M / 2);
    int kh = kp_g >> 4, kp = kp_g & 15;
    int k0 = 2 * kp_g;
    float x0, x1;
    if (transpose) { x0 = w[((size_t)k0 * M + m) * 128 + n]; x1 = w[((size_t)(k0 + 1) * M + m) * 128 + n]; }
    else           { x0 = w[((size_t)m * M + k0) * 128 + n]; x1 = w[((size_t)m * M + k0 + 1) * 128 + n]; }
    uint32_t hi, lo;
    split_pack(x0, x1, hi, lo);
    int np = (n & 7) * 16 + (n >> 3);
    size_t base = ((size_t)(m * (M / 32) + kh)) * 4096;
    dst[base + (size_t)kp * 128 + np] = hi;
    dst[base + 2048 + (size_t)kp * 128 + np] = lo;
}

// ============ Kernel P: ds = c*(ss + inv_sqrt3*vv), P-form ============
template <int M>
__global__ __launch_bounds__(512, 1)
void tp_p_kernel(const float* __restrict__ s1, const float* __restrict__ v1,
                 const float* __restrict__ s2, const float* __restrict__ v2,
                 const uint32_t* __restrict__ wp, float* __restrict__ ts, float cscale) {
    extern __shared__ uint32_t dsm[];                 // 2*4224 words
    constexpr int PSTR = M * M * 128;
    const uint32_t smem_base = smem_u32(dsm);
    const int tid = threadIdx.x, wid = tid >> 5, lane = tid & 31;
    const int rq = wid >> 2, ng = wid & 3;
    const int g = lane >> 2, t4 = lane & 3;
    const int bb = blockIdx.x * 64;
    const int gb0 = bb + rq * 16 + g, gb1 = gb0 + 8;

    float acc[4][4];
#pragma unroll
    for (int nt = 0; nt < 4; ++nt)
#pragma unroll
        for (int j = 0; j < 4; ++j) acc[nt][j] = 0.f;

    const float* s1r0 = s1 + (size_t)gb0 * M;
    const float* s1r1 = s1 + (size_t)gb1 * M;
    const float* s2r0 = s2 + (size_t)gb0 * M;
    const float* s2r1 = s2 + (size_t)gb1 * M;
    const float *v1r0[3], *v1r1[3], *v2r0[3], *v2r1[3];
#pragma unroll
    for (int i = 0; i < 3; ++i) {
        v1r0[i] = v1 + (size_t)i * PLANE + (size_t)gb0 * M;
        v1r1[i] = v1 + (size_t)i * PLANE + (size_t)gb1 * M;
        v2r0[i] = v2 + (size_t)i * PLANE + (size_t)gb0 * M;
        v2r1[i] = v2 + (size_t)i * PLANE + (size_t)gb1 * M;
    }

    auto docopy = [&](int blk, int b) {
        const uint32_t sb0 = smem_base + (uint32_t)(b * 4224) * 4;
#pragma unroll
        for (int i = 0; i < 2; ++i) {
            int sg = tid + 512 * i;                 // 0..1023
            int c = sg & 31, kp = (sg >> 5) & 7, h = (sg >> 8) & 1, pl = sg >> 9;
            const uint32_t* src = wp + (size_t)pl * PSTR + (size_t)blk * 2048 + h * 1024 + kp * 128 + c * 4;
            CP_ASYNC16(sb0 + (uint32_t)((((pl * 2 + h) * 8 + kp) * 132 + c * 4) * 4), src);
        }
    };

    for (int vw = 0; vw < M / 16; ++vw) {
        const int v0w = vw * 16;
        docopy(vw * M, 0);
        CP_COMMIT();
        for (int u = 0; u < M; ++u) {
            const int cur = u & 1;
            if (u + 1 < M) { docopy(vw * M + u + 1, cur ^ 1); CP_COMMIT(); CP_WAIT1(); }
            else CP_WAIT0();
            __syncthreads();

            float s1a[2], v1a[3][2];
            s1a[0] = __ldg(s1r0 + u); s1a[1] = __ldg(s1r1 + u);
#pragma unroll
            for (int i = 0; i < 3; ++i) { v1a[i][0] = __ldg(v1r0[i] + u); v1a[i][1] = __ldg(v1r1[i] + u); }
            const int ca = v0w + 2 * t4, cb = ca + 8;
            float s2v[2][4], v2v[3][2][4];
            {
                float2 A, B;
                A = __ldg((const float2*)(s2r0 + ca)); B = __ldg((const float2*)(s2r0 + cb));
                s2v[0][0]=A.x; s2v[0][1]=A.y; s2v[0][2]=B.x; s2v[0][3]=B.y;
                A = __ldg((const float2*)(s2r1 + ca)); B = __ldg((const float2*)(s2r1 + cb));
                s2v[1][0]=A.x; s2v[1][1]=A.y; s2v[1][2]=B.x; s2v[1][3]=B.y;
#pragma unroll
                for (int i = 0; i < 3; ++i) {
                    A = __ldg((const float2*)(v2r0[i] + ca)); B = __ldg((const float2*)(v2r0[i] + cb));
                    v2v[i][0][0]=A.x; v2v[i][0][1]=A.y; v2v[i][0][2]=B.x; v2v[i][0][3]=B.y;
                    A = __ldg((const float2*)(v2r1[i] + ca)); B = __ldg((const float2*)(v2r1[i] + cb));
                    v2v[i][1][0]=A.x; v2v[i][1][1]=A.y; v2v[i][1][2]=B.x; v2v[i][1][3]=B.y;
                }
            }
            float pav[2][4], pbv[2][4];
#pragma unroll
            for (int r = 0; r < 2; ++r)
#pragma unroll
                for (int j = 0; j < 4; ++j) {
                    pav[r][j] = s1a[r] * s2v[r][j];
                    pbv[r][j] = INV_SQRT3 * (v1a[0][r] * v2v[0][r][j] +
                                             v1a[1][r] * v2v[1][r][j] +
                                             v1a[2][r] * v2v[2][r][j]);
                }
            const uint32_t* bufb = dsm + cur * 4224;
            const int boff = g * 16 + ng * 4;
#pragma unroll
            for (int st = 0; st < 2; ++st) {        // 0=ss(parts0,1) 1=vv(parts2,3)
                float (*pv)[4] = st ? pbv : pav;
                uint32_t fh[4], fl[4];
                split_pack(pv[0][0], pv[0][1], fh[0], fl[0]);
                split_pack(pv[1][0], pv[1][1], fh[1], fl[1]);
                split_pack(pv[0][2], pv[0][3], fh[2], fl[2]);
                split_pack(pv[1][2], pv[1][3], fh[3], fl[3]);
                const uint32_t* h0p = bufb + ((st * 2) * 8 + t4) * 132 + boff;
                const uint32_t* h1p = bufb + ((st * 2) * 8 + t4 + 4) * 132 + boff;
                uint4 H0 = *(const uint4*)h0p, H1 = *(const uint4*)h1p;
                uint4 L0 = *(const uint4*)(h0p + 8 * 132), L1 = *(const uint4*)(h1p + 8 * 132);
                uint32_t h0a[4]={H0.x,H0.y,H0.z,H0.w}, h1a[4]={H1.x,H1.y,H1.z,H1.w};
                uint32_t l0a[4]={L0.x,L0.y,L0.z,L0.w}, l1a[4]={L1.x,L1.y,L1.z,L1.w};
#pragma unroll
                for (int j = 0; j < 4; ++j) {
                    float* d = acc[j];
                    MMA_BF16(d, fh[0], fh[1], fh[2], fh[3], h0a[j], h1a[j]);
                    MMA_BF16(d, fl[0], fl[1], fl[2], fl[3], h0a[j], h1a[j]);
                    MMA_BF16(d, fh[0], fh[1], fh[2], fh[3], l0a[j], l1a[j]);
                }
            }
            __syncthreads();
        }
    }
#pragma unroll
    for (int nt = 0; nt < 4; ++nt) {
        const int col = ng * 32 + nt * 8 + 2 * t4;
        *(float2*)(ts + (size_t)gb0 * 128 + col) = make_float2(cscale * acc[nt][0], cscale * acc[nt][1]);
        *(float2*)(ts + (size_t)gb1 * 128 + col) = make_float2(cscale * acc[nt][2], cscale * acc[nt][3]);
    }
}

// ============ Kernel V: dv_i = c*sum_m( v2_i[b,m]*Tsv_m + v1_i[b,m]*Tvs_m ) ==
template <int M>
__global__ __launch_bounds__(512, 1)
void tp_v_kernel(const float* __restrict__ s1, const float* __restrict__ v1,
                 const float* __restrict__ s2, const float* __restrict__ v2,
                 const uint32_t* __restrict__ wv, float* __restrict__ tv, float cscale) {
    extern __shared__ uint32_t dsm[];       // Wbuf 2*8448 | Afrag 16*NKT*128
    constexpr int NKT = M / 16, NCHK = M / 32, NCT = M * NCHK;
    constexpr int PSTR = M * M * 128;
    uint32_t* afrag = dsm + 16896;
    const uint32_t smem_base = smem_u32(dsm);
    const int tid = threadIdx.x, wid = tid >> 5, lane = tid & 31;
    const int rq = wid >> 2, ng = wid & 3;
    const int g = lane >> 2, t4 = lane & 3;
    const int bb = blockIdx.x * 64;
    const int gb0 = bb + rq * 16 + g, gb1 = gb0 + 8;

    float Tsv[4][4], Tvs[4][4], dv[3][4][4];
#pragma unroll
    for (int nt = 0; nt < 4; ++nt)
#pragma unroll
        for (int j = 0; j < 4; ++j) {
            Tsv[nt][j] = 0.f; Tvs[nt][j] = 0.f;
            dv[0][nt][j] = 0.f; dv[1][nt][j] = 0.f; dv[2][nt][j] = 0.f;
        }

    auto docopy = [&](int ci, int b) {
        const uint32_t sb0 = smem_base + (uint32_t)(b * 8448) * 4;
#pragma unroll
        for (int i = 0; i < 4; ++i) {
            int sg = tid + 512 * i;                 // 0..2047
            int c = sg & 31, kp = (sg >> 5) & 15, h = (sg >> 9) & 1, s = sg >> 10;
            const uint32_t* src = wv + (size_t)s * PSTR + (size_t)ci * 4096 + h * 2048 + kp * 128 + c * 4;
            CP_ASYNC16(sb0 + (uint32_t)((((s * 2 + h) * 16 + kp) * 132 + c * 4) * 4), src);
        }
    };

    docopy(0, 0);
    CP_COMMIT();

    // build A fragments: [s*2+hilo][rq][kt][lane][4]; stream0 A=s1, stream1 A=s2
    for (int it = tid; it < 2 * 4 * NKT * 32; it += 512) {
        int ln = it & 31;
        int kt = (it >> 5) % NKT;
        int rr = ((it >> 5) / NKT) % 4;
        int s  = (it >> 5) / NKT / 4;
        const float* src = s ? s2 : s1;
        int r0 = bb + rr * 16 + (ln >> 2);
        int kp0 = kt * 8 + (ln & 3);
        uint32_t h[4], l[4];
        float2 x;
        x = *(const float2*)(src + (size_t)r0 * M + 2 * kp0);           split_pack(x.x, x.y, h[0], l[0]);
        x = *(const float2*)(src + (size_t)(r0 + 8) * M + 2 * kp0);     split_pack(x.x, x.y, h[1], l[1]);
        x = *(const float2*)(src + (size_t)r0 * M + 2 * (kp0 + 4));     split_pack(x.x, x.y, h[2], l[2]);
        x = *(const float2*)(src + (size_t)(r0 + 8) * M + 2 * (kp0 + 4)); split_pack(x.x, x.y, h[3], l[3]);
        uint32_t* ah = afrag + (((size_t)(s * 2 + 0) * 4 + rr) * NKT + kt) * 128 + ln * 4;
        uint32_t* al = afrag + (((size_t)(s * 2 + 1) * 4 + rr) * NKT + kt) * 128 + ln * 4;
        *(uint4*)ah = make_uint4(h[0], h[1], h[2], h[3]);
        *(uint4*)al = make_uint4(l[0], l[1], l[2], l[3]);
    }
    __syncthreads();

    int m = 0, c = 0;
    for (int ci = 0; ci < NCT; ++ci) {
        const int cur = ci & 1;
        if (ci + 1 < NCT) { docopy(ci + 1, cur ^ 1); CP_COMMIT(); CP_WAIT1(); }
        else CP_WAIT0();
        __syncthreads();

        const uint32_t* bufb = dsm + cur * 8448;
        const int boff = g * 16 + ng * 4;
#pragma unroll
        for (int j = 0; j < 2; ++j) {               // ktile within chunk
            const int kt = c * 2 + j;
            uint4 Ah = *(const uint4*)(afrag + (((size_t)0 * 4 + rq) * NKT + kt) * 128 + lane * 4);
            uint4 Al = *(const uint4*)(afrag + (((size_t)1 * 4 + rq) * NKT + kt) * 128 + lane * 4);
            uint4 Ch = *(const uint4*)(afrag + (((size_t)2 * 4 + rq) * NKT + kt) * 128 + lane * 4);
            uint4 Cl = *(const uint4*)(afrag + (((size_t)3 * 4 + rq) * NKT + kt) * 128 + lane * 4);
            const uint32_t* b0h = bufb + (0 * 16 + j * 8 + t4) * 132 + boff;
            const uint32_t* b1h = bufb + (0 * 16 + j * 8 + 4 + t4) * 132 + boff;
            uint4 BH0 = *(const uint4*)b0h, BH1 = *(const uint4*)b1h;
            uint4 BL0 = *(const uint4*)(b0h + 16 * 132), BL1 = *(const uint4*)(b1h + 16 * 132);
            const uint32_t* d0h = bufb + (2 * 16 + j * 8 + t4) * 132 + boff;
            const uint32_t* d1h = bufb + (2 * 16 + j * 8 + 4 + t4) * 132 + boff;
            uint4 DH0 = *(const uint4*)d0h, DH1 = *(const uint4*)d1h;
            uint4 DL0 = *(const uint4*)(d0h + 16 * 132), DL1 = *(const uint4*)(d1h + 16 * 132);
            uint32_t bh0[4]={BH0.x,BH0.y,BH0.z,BH0.w}, bh1[4]={BH1.x,BH1.y,BH1.z,BH1.w};
            uint32_t bl0[4]={BL0.x,BL0.y,BL0.z,BL0.w}, bl1[4]={BL1.x,BL1.y,BL1.z,BL1.w};
            uint32_t dh0[4]={DH0.x,DH0.y,DH0.z,DH0.w}, dh1[4]={DH1.x,DH1.y,DH1.z,DH1.w};
            uint32_t dl0[4]={DL0.x,DL0.y,DL0.z,DL0.w}, dl1[4]={DL1.x,DL1.y,DL1.z,DL1.w};
#pragma unroll
            for (int nt = 0; nt < 4; ++nt) {
                MMA_BF16(Tsv[nt], Ah.x, Ah.y, Ah.z, Ah.w, bh0[nt], bh1[nt]);
                MMA_BF16(Tsv[nt], Al.x, Al.y, Al.z, Al.w, bh0[nt], bh1[nt]);
                MMA_BF16(Tsv[nt], Ah.x, Ah.y, Ah.z, Ah.w, bl0[nt], bl1[nt]);
                MMA_BF16(Tvs[nt], Ch.x, Ch.y, Ch.z, Ch.w, dh0[nt], dh1[nt]);
                MMA_BF16(Tvs[nt], Cl.x, Cl.y, Cl.z, Cl.w, dh0[nt], dh1[nt]);
                MMA_BF16(Tvs[nt], Ch.x, Ch.y, Ch.z, Ch.w, dl0[nt], dl1[nt]);
            }
        }

        if (c == NCHK - 1) {
            float sv0[3], sv1[3], vs0[3], vs1[3];
#pragma unroll
            for (int i = 0; i < 3; ++i) {
                sv0[i] = __ldg(v2 + (size_t)i * PLANE + (size_t)gb0 * M + m);
                sv1[i] = __ldg(v2 + (size_t)i * PLANE + (size_t)gb1 * M + m);
                vs0[i] = __ldg(v1 + (size_t)i * PLANE + (size_t)gb0 * M + m);
                vs1[i] = __ldg(v1 + (size_t)i * PLANE + (size_t)gb1 * M + m);
            }
#pragma unroll
            for (int i = 0; i < 3; ++i)
#pragma unroll
                for (int nt = 0; nt < 4; ++nt) {
                    dv[i][nt][0] += sv0[i] * Tsv[nt][0] + vs0[i] * Tvs[nt][0];
                    dv[i][nt][1] += sv0[i] * Tsv[nt][1] + vs0[i] * Tvs[nt][1];
                    dv[i][nt][2] += sv1[i] * Tsv[nt][2] + vs1[i] * Tvs[nt][2];
                    dv[i][nt][3] += sv1[i] * Tsv[nt][3] + vs1[i] * Tvs[nt][3];
                }
#pragma unroll
            for (int nt = 0; nt < 4; ++nt)
#pragma unroll
                for (int j2 = 0; j2 < 4; ++j2) { Tsv[nt][j2] = 0.f; Tvs[nt][j2] = 0.f; }
            ++m; c = 0;
        } else ++c;
        __syncthreads();
    }

#pragma unroll
    for (int i = 0; i < 3; ++i) {
        float* op = tv + (size_t)i * PLANE;
#pragma unroll
        for (int nt = 0; nt < 4; ++nt) {
            const int col = ng * 32 + nt * 8 + 2 * t4;
            *(float2*)(op + (size_t)gb0 * 128 + col) = make_float2(cscale * dv[i][nt][0], cscale * dv[i][nt][1]);
            *(float2*)(op + (size_t)gb1 * 128 + col) = make_float2(cscale * dv[i][nt][2], cscale * dv[i][nt][3]);
        }
    }
}

// ============ split / pack / gemm / gate ============
__global__ void split_kernel(const float* __restrict__ x,
                             float* __restrict__ s, float* __restrict__ v) {
    int i = blockIdx.x * 256 + threadIdx.x;
    if (i >= BATCH * 64) return;
    int b = i >> 6, u = i & 63;
    const float* xr = x + b * 256;
    s[i] = xr[u];
    v[0 * PLANE + i] = xr[64 + 3 * u + 0];
    v[1 * PLANE + i] = xr[64 + 3 * u + 1];
    v[2 * PLANE + i] = xr[64 + 3 * u + 2];
}
__global__ void pack_kernel(const float* __restrict__ s,
                            const float* __restrict__ v, float* __restrict__ out) {
    int i = blockIdx.x * 256 + threadIdx.x;
    if (i >= BATCH * 64) return;
    int b = i >> 6, u = i & 63;
    float* orow = out + b * 256;
    orow[u] = s[i];
    orow[64 + 3 * u + 0] = v[0 * PLANE + i];
    orow[64 + 3 * u + 1] = v[1 * PLANE + i];
    orow[64 + 3 * u + 2] = v[2 * PLANE + i];
}
template <int NC>
__global__ __launch_bounds__(256)
void gemm_kernel(const float* __restrict__ X, const float* __restrict__ Wm,
                 float* __restrict__ Y, int K, float scale) {
    constexpr int N = 32 * NC;
    X += (size_t)blockIdx.y * PLANE;
    Y += (size_t)blockIdx.y * PLANE;
    __shared__ float Xs[32][33];
    __shared__ float Ws[32][N + 1];
    const int tx = threadIdx.x, ty = threadIdx.y;
    const int tid = ty * 32 + tx;
    const int row0 = blockIdx.x * 32;
    float acc[4][NC];
#pragma unroll
    for (int r = 0; r < 4; ++r)
#pragma unroll
        for (int j = 0; j < NC; ++j) acc[r][j] = 0.f;
    for (int k0 = 0; k0 < K; k0 += 32) {
#pragma unroll
        for (int e = tid; e < 32 * 32; e += 256) {
            int r = e >> 5, kk = e & 31;
            Xs[r][kk] = X[(size_t)(row0 + r) * K + k0 + kk];
        }
        for (int e = tid; e < 32 * N; e += 256) {
            int kk = e / N, n = e - kk * N;
            Ws[kk][n] = Wm[(size_t)(k0 + kk) * N + n];
        }
        __syncthreads();
#pragma unroll 8
        for (int kk = 0; kk < 32; ++kk) {
            float wvv[NC];
#pragma unroll
            for (int j = 0; j < NC; ++j) wvv[j] = Ws[kk][tx * NC + j];
#pragma unroll
            for (int r = 0; r < 4; ++r) {
                float xv = Xs[ty * 4 + r][kk];
#pragma unroll
                for (int j = 0; j < NC; ++j) acc[r][j] += xv * wvv[j];
            }
        }
        __syncthreads();
    }
#pragma unroll
    for (int r = 0; r < 4; ++r)
#pragma unroll
        for (int j = 0; j < NC; ++j)
            Y[(size_t)(row0 + ty * 4 + r) * N + tx * NC + j] = scale * acc[r][j];
}
__global__ void gate_kernel(const float* __restrict__ sl, const float* __restrict__ g,
                            const float* __restrict__ vl,
                            float* __restrict__ gs, float* __restrict__ gv) {
    int i = blockIdx.x * 256 + threadIdx.x;
    if (i >= BATCH * 128) return;
    gs[i] = GAIN * tanhf(sl[i]);
    float t = GAIN * tanhf(g[i]);
    gv[0 * PLANE + i] = t * vl[0 * PLANE + i];
    gv[1 * PLANE + i] = t * vl[1 * PLANE + i];
    gv[2 * PLANE + i] = t * vl[2 * PLANE + i];
}

static inline void run_gemm(const float* X, const float* W, float* Y,
                            int K, int N, float scale, int planes) {
    dim3 blk(32, 8), grd(BATCH / 32, planes);
    if (N == 64) gemm_kernel<2><<<grd, blk>>>(X, W, Y, K, scale);
    else         gemm_kernel<4><<<grd, blk>>>(X, W, Y, K, scale);
}

extern "C" void kernel_launch(void* const* d_in, const int* in_sizes, int n_in,
                              void* d_out, int out_size) {
    const float* in[29];
    for (int i = 0; i < 29; ++i) in[i] = (const float*)d_in[i];
    float* out = (float*)d_out;

    float *s, *v, *s1, *v1, *s2, *v2, *ts, *tv;
    uint32_t *wp1, *wp2, *wv1, *wv2;
    cudaGetSymbolAddress((void**)&s,  g_s);
    cudaGetSymbolAddress((void**)&v,  g_v);
    cudaGetSymbolAddress((void**)&s1, g_s1);
    cudaGetSymbolAddress((void**)&v1, g_v1);
    cudaGetSymbolAddress((void**)&s2, g_s2);
    cudaGetSymbolAddress((void**)&v2, g_v2);
    cudaGetSymbolAddress((void**)&ts, g_ts);
    cudaGetSymbolAddress((void**)&tv, g_tv);
    cudaGetSymbolAddress((void**)&wp1, g_wp1);
    cudaGetSymbolAddress((void**)&wp2, g_wp2);
    cudaGetSymbolAddress((void**)&wv1, g_wv1);
    cudaGetSymbolAddress((void**)&wv2, g_wv2);

    const int P_SMEM  = 2 * 4224 * 4;                       // 33792
    const int V_SMEM1 = (16896 + 16 * 4 * 128) * 4;         // 100352
    const int V_SMEM2 = (16896 + 16 * 8 * 128) * 4;         // 133120
    cudaFuncSetAttribute(tp_p_kernel<64>,  cudaFuncAttributeMaxDynamicSharedMemorySize, P_SMEM);
    cudaFuncSetAttribute(tp_p_kernel<128>, cudaFuncAttributeMaxDynamicSharedMemorySize, P_SMEM);
    cudaFuncSetAttribute(tp_v_kernel<64>,  cudaFuncAttributeMaxDynamicSharedMemorySize, V_SMEM1);
    cudaFuncSetAttribute(tp_v_kernel<128>, cudaFuncAttributeMaxDynamicSharedMemorySize, V_SMEM2);

    const float c64  = 0.125f;
    const float c128 = 0.08838834764831845f;
    const float ctp1 = 1.0f / (64.0f  * 1.4142135623730951f);
    const float ctp2 = 1.0f / (128.0f * 1.4142135623730951f);

    // prepass
    {
        const int t1 = (64 * 64 / 2) * 128, t2 = (128 * 128 / 2) * 128;
        const int p1 = 64 * 64 * 128, p2 = 128 * 128 * 128;
        pack_weights_kernel<<<(t1 + 255) / 256, 256>>>(in[5], wp1, 64);
        pack_weights_kernel<<<(t1 + 255) / 256, 256>>>(in[6], wp1 + p1, 64);
        pack_weights_v_kernel<<<(t1 + 255) / 256, 256>>>(in[7], wv1, 64, 1);
        pack_weights_v_kernel<<<(t1 + 255) / 256, 256>>>(in[8], wv1 + p1, 64, 0);
        pack_weights_kernel<<<(t2 + 255) / 256, 256>>>(in[18], wp2, 128);
        pack_weights_kernel<<<(t2 + 255) / 256, 256>>>(in[19], wp2 + p2, 128);
        pack_weights_v_kernel<<<(t2 + 255) / 256, 256>>>(in[20], wv2, 128, 1);
        pack_weights_v_kernel<<<(t2 + 255) / 256, 256>>>(in[21], wv2 + p2, 128, 0);
    }

    split_kernel<<<BATCH * 64 / 256, 256>>>(in[0], s, v);

    // block 1
    run_gemm(s, in[1], s1, 64, 64, c64, 1);
    run_gemm(v, in[2], v1, 64, 64, c64, 3);
    run_gemm(s, in[3], s2, 64, 64, c64, 1);
    run_gemm(v, in[4], v2, 64, 64, c64, 3);
    tp_p_kernel<64><<<BATCH / 64, 512, P_SMEM>>>(s1, v1, s2, v2, wp1, ts, ctp1);
    tp_v_kernel<64><<<BATCH / 64, 512, V_SMEM1>>>(s1, v1, s2, v2, wv1, tv, ctp1);
    run_gemm(ts, in[9],  s1, 128, 128, c128, 1);
    run_gemm(ts, in[10], s2, 128, 128, c128, 1);
    run_gemm(tv, in[11], v1, 128, 128, c128, 3);
    gate_kernel<<<BATCH * 128 / 256, 256>>>(s1, s2, v1, ts, tv);
    run_gemm(ts, in[12], s, 128, 128, c128, 1);
    run_gemm(tv, in[13], v, 128, 128, c128, 3);

    // block 2
    run_gemm(s, in[14], s1, 128, 128, c128, 1);
    run_gemm(v, in[15], v1, 128, 128, c128, 3);
    run_gemm(s, in[16], s2, 128, 128, c128, 1);
    run_gemm(v, in[17], v2, 128, 128, c128, 3);
    tp_p_kernel<128><<<BATCH / 64, 512, P_SMEM>>>(s1, v1, s2, v2, wp2, ts, ctp2);
    tp_v_kernel<128><<<BATCH / 64, 512, V_SMEM2>>>(s1, v1, s2, v2, wv2, tv, ctp2);
    run_gemm(ts, in[22], s1, 128, 128, c128, 1);
    run_gemm(ts, in[23], s2, 128, 128, c128, 1);
    run_gemm(tv, in[24], v1, 128, 128, c128, 3);
    gate_kernel<<<BATCH * 128 / 256, 256>>>(s1, s2, v1, ts, tv);
    run_gemm(ts, in[25], s, 128, 128, c128, 1);
    run_gemm(tv, in[26], v, 128, 128, c128, 3);

    // final
    run_gemm(s, in[27], s1, 128, 64, c128, 1);
    run_gemm(v, in[28], v1, 128, 64, c128, 3);
    pack_kernel<<<BATCH * 64 / 256, 256>>>(s1, v1, out);
}

// round 8
// speedup vs baseline: 2.0925x; 1.4368x over previous
#include <cuda_runtime.h>
#include <cstdint>
#include <math.h>

#define BATCH 8192
#define PLANE (8192 * 128)
#define GAIN 1.5927116870880127f
#define INV_SQRT3 0.57735026918962576f

__device__ float g_s [PLANE];
__device__ float g_v [3 * PLANE];
__device__ float g_s1[PLANE];
__device__ float g_v1[3 * PLANE];
__device__ float g_s2[PLANE];
__device__ float g_v2[3 * PLANE];
__device__ float g_ts[PLANE];
__device__ float g_tv[3 * PLANE];
__device__ uint32_t g_wp1[2u * 64 * 64 * 128];
__device__ uint32_t g_wp2[2u * 128 * 128 * 128];
__device__ uint32_t g_wv1[2u * 64 * 64 * 128];
__device__ uint32_t g_wv2[2u * 128 * 128 * 128];

__device__ __forceinline__ uint32_t smem_u32(const void* p) {
    uint32_t a;
    asm("{ .reg .u64 t; cvta.to.shared.u64 t, %1; cvt.u32.u64 %0, t; }" : "=r"(a) : "l"(p));
    return a;
}
#define MMA_BF16(d, a0, a1, a2, a3, b0, b1)                                 \
    asm volatile(                                                           \
        "mma.sync.aligned.m16n8k16.row.col.f32.bf16.bf16.f32 "              \
        "{%0,%1,%2,%3}, {%4,%5,%6,%7}, {%8,%9}, {%0,%1,%2,%3};"             \
        : "+f"((d)[0]), "+f"((d)[1]), "+f"((d)[2]), "+f"((d)[3])            \
        : "r"(a0), "r"(a1), "r"(a2), "r"(a3), "r"(b0), "r"(b1))
#define CP_ASYNC16(sa, gp) \
    asm volatile("cp.async.ca.shared.global [%0], [%1], 16;" :: "r"(sa), "l"(gp) : "memory")
#define CP_COMMIT() asm volatile("cp.async.commit_group;" ::: "memory")
#define CP_WAIT1()  asm volatile("cp.async.wait_group 1;" ::: "memory")
#define CP_WAIT0()  asm volatile("cp.async.wait_group 0;" ::: "memory")

__device__ __forceinline__ void split_pack(float x0, float x1,
                                           uint32_t& hi, uint32_t& lo) {
    uint32_t h;
    asm("cvt.rn.bf16x2.f32 %0, %1, %2;" : "=r"(h) : "f"(x1), "f"(x0));
    float l0 = x0 - __uint_as_float(h << 16);
    float l1 = x1 - __uint_as_float(h & 0xFFFF0000u);
    asm("cvt.rn.bf16x2.f32 %0, %1, %2;" : "=r"(lo) : "f"(l1), "f"(l0));
    hi = h;
}

// P-form prepass
__global__ void pack_weights_kernel(const float* __restrict__ w,
                                    uint32_t* __restrict__ dst, int M) {
    int idx = blockIdx.x * 256 + threadIdx.x;
    if (idx >= (M * M / 2) * 128) return;
    int kpair = idx >> 7, n = idx & 127;
    int u = kpair / (M / 2), rem = kpair % (M / 2);
    int vw = rem >> 3, kp = rem & 7;
    int v = vw * 16 + 2 * kp;
    uint32_t hi, lo;
    split_pack(w[((size_t)u * M + v) * 128 + n], w[((size_t)u * M + v + 1) * 128 + n], hi, lo);
    int np = (n & 7) * 16 + (n >> 3);
    size_t base = ((size_t)(vw * M + u)) * 2048;
    dst[base + kp * 128 + np] = hi;
    dst[base + 1024 + kp * 128 + np] = lo;
}
// V-form prepass
__global__ void pack_weights_v_kernel(const float* __restrict__ w,
                                      uint32_t* __restrict__ dst, int M, int transpose) {
    int idx = blockIdx.x * 256 + threadIdx.x;
    if (idx >= (M * M / 2) * 128) return;
    int gkp = idx >> 7, n = idx & 127;
    int m = gkp / (M / 2), kp_g = gkp % (M / 2);
    int kh = kp_g >> 4, kp = kp_g & 15;
    int k0 = 2 * kp_g;
    float x0, x1;
    if (transpose) { x0 = w[((size_t)k0 * M + m) * 128 + n]; x1 = w[((size_t)(k0 + 1) * M + m) * 128 + n]; }
    else           { x0 = w[((size_t)m * M + k0) * 128 + n]; x1 = w[((size_t)m * M + k0 + 1) * 128 + n]; }
    uint32_t hi, lo;
    split_pack(x0, x1, hi, lo);
    int np = (n & 7) * 16 + (n >> 3);
    size_t base = ((size_t)(m * (M / 32) + kh)) * 4096;
    dst[base + (size_t)kp * 128 + np] = hi;
    dst[base + 2048 + (size_t)kp * 128 + np] = lo;
}

// ============ Kernel P: 32-row CTA, 256 thr, 2 CTAs/SM ============
template <int M>
__global__ __launch_bounds__(256, 2)
void tp_p_kernel(const float* __restrict__ s1, const float* __restrict__ v1,
                 const float* __restrict__ s2, const float* __restrict__ v2,
                 const uint32_t* __restrict__ wp, float* __restrict__ ts, float cscale) {
    extern __shared__ uint32_t dsm[];                 // 2*4224 words
    constexpr int PSTR = M * M * 128;
    const uint32_t smem_base = smem_u32(dsm);
    const int tid = threadIdx.x, wid = tid >> 5, lane = tid & 31;
    const int rq = wid >> 2, ng = wid & 3;            // rq in {0,1}
    const int g = lane >> 2, t4 = lane & 3;
    const int bb = blockIdx.x * 32;
    const int gb0 = bb + rq * 16 + g, gb1 = gb0 + 8;

    float acc[4][4];
#pragma unroll
    for (int nt = 0; nt < 4; ++nt)
#pragma unroll
        for (int j = 0; j < 4; ++j) acc[nt][j] = 0.f;

    const float* s1r0 = s1 + (size_t)gb0 * M;
    const float* s1r1 = s1 + (size_t)gb1 * M;
    const float* s2r0 = s2 + (size_t)gb0 * M;
    const float* s2r1 = s2 + (size_t)gb1 * M;
    const float *v1r0[3], *v1r1[3], *v2r0[3], *v2r1[3];
#pragma unroll
    for (int i = 0; i < 3; ++i) {
        v1r0[i] = v1 + (size_t)i * PLANE + (size_t)gb0 * M;
        v1r1[i] = v1 + (size_t)i * PLANE + (size_t)gb1 * M;
        v2r0[i] = v2 + (size_t)i * PLANE + (size_t)gb0 * M;
        v2r1[i] = v2 + (size_t)i * PLANE + (size_t)gb1 * M;
    }

    auto docopy = [&](int blk, int b) {
        const uint32_t sb0 = smem_base + (uint32_t)(b * 4224) * 4;
#pragma unroll
        for (int i = 0; i < 4; ++i) {
            int sg = tid + 256 * i;                 // 0..1023
            int c = sg & 31, kp = (sg >> 5) & 7, h = (sg >> 8) & 1, pl = sg >> 9;
            const uint32_t* src = wp + (size_t)pl * PSTR + (size_t)blk * 2048 + h * 1024 + kp * 128 + c * 4;
            CP_ASYNC16(sb0 + (uint32_t)((((pl * 2 + h) * 8 + kp) * 132 + c * 4) * 4), src);
        }
    };

    for (int vw = 0; vw < M / 16; ++vw) {
        const int v0w = vw * 16;
        // a2 operands: loop-invariant in u — load once per window
        const int ca = v0w + 2 * t4, cb = ca + 8;
        float s2v[2][4], v2v[3][2][4];
        {
            float2 A, B;
            A = __ldg((const float2*)(s2r0 + ca)); B = __ldg((const float2*)(s2r0 + cb));
            s2v[0][0]=A.x; s2v[0][1]=A.y; s2v[0][2]=B.x; s2v[0][3]=B.y;
            A = __ldg((const float2*)(s2r1 + ca)); B = __ldg((const float2*)(s2r1 + cb));
            s2v[1][0]=A.x; s2v[1][1]=A.y; s2v[1][2]=B.x; s2v[1][3]=B.y;
#pragma unroll
            for (int i = 0; i < 3; ++i) {
                A = __ldg((const float2*)(v2r0[i] + ca)); B = __ldg((const float2*)(v2r0[i] + cb));
                v2v[i][0][0]=A.x; v2v[i][0][1]=A.y; v2v[i][0][2]=B.x; v2v[i][0][3]=B.y;
                A = __ldg((const float2*)(v2r1[i] + ca)); B = __ldg((const float2*)(v2r1[i] + cb));
                v2v[i][1][0]=A.x; v2v[i][1][1]=A.y; v2v[i][1][2]=B.x; v2v[i][1][3]=B.y;
            }
        }

        docopy(vw * M, 0);
        CP_COMMIT();
        for (int u = 0; u < M; ++u) {
            const int cur = u & 1;
            if (u + 1 < M) { docopy(vw * M + u + 1, cur ^ 1); CP_COMMIT(); CP_WAIT1(); }
            else CP_WAIT0();
            __syncthreads();

            float s1a[2], v1a[3][2];
            s1a[0] = __ldg(s1r0 + u); s1a[1] = __ldg(s1r1 + u);
#pragma unroll
            for (int i = 0; i < 3; ++i) { v1a[i][0] = __ldg(v1r0[i] + u); v1a[i][1] = __ldg(v1r1[i] + u); }

            float pav[2][4], pbv[2][4];
#pragma unroll
            for (int r = 0; r < 2; ++r)
#pragma unroll
                for (int j = 0; j < 4; ++j) {
                    pav[r][j] = s1a[r] * s2v[r][j];
                    pbv[r][j] = INV_SQRT3 * (v1a[0][r] * v2v[0][r][j] +
                                             v1a[1][r] * v2v[1][r][j] +
                                             v1a[2][r] * v2v[2][r][j]);
                }
            const uint32_t* bufb = dsm + cur * 4224;
            const int boff = g * 16 + ng * 4;
#pragma unroll
            for (int st = 0; st < 2; ++st) {
                float (*pv)[4] = st ? pbv : pav;
                uint32_t fh[4], fl[4];
                split_pack(pv[0][0], pv[0][1], fh[0], fl[0]);
                split_pack(pv[1][0], pv[1][1], fh[1], fl[1]);
                split_pack(pv[0][2], pv[0][3], fh[2], fl[2]);
                split_pack(pv[1][2], pv[1][3], fh[3], fl[3]);
                const uint32_t* h0p = bufb + ((st * 2) * 8 + t4) * 132 + boff;
                const uint32_t* h1p = bufb + ((st * 2) * 8 + t4 + 4) * 132 + boff;
                uint4 H0 = *(const uint4*)h0p, H1 = *(const uint4*)h1p;
                uint4 L0 = *(const uint4*)(h0p + 8 * 132), L1 = *(const uint4*)(h1p + 8 * 132);
                uint32_t h0a[4]={H0.x,H0.y,H0.z,H0.w}, h1a[4]={H1.x,H1.y,H1.z,H1.w};
                uint32_t l0a[4]={L0.x,L0.y,L0.z,L0.w}, l1a[4]={L1.x,L1.y,L1.z,L1.w};
#pragma unroll
                for (int j = 0; j < 4; ++j) {
                    float* d = acc[j];
                    MMA_BF16(d, fh[0], fh[1], fh[2], fh[3], h0a[j], h1a[j]);
                    MMA_BF16(d, fl[0], fl[1], fl[2], fl[3], h0a[j], h1a[j]);
                    MMA_BF16(d, fh[0], fh[1], fh[2], fh[3], l0a[j], l1a[j]);
                }
            }
            __syncthreads();
        }
    }
#pragma unroll
    for (int nt = 0; nt < 4; ++nt) {
        const int col = ng * 32 + nt * 8 + 2 * t4;
        *(float2*)(ts + (size_t)gb0 * 128 + col) = make_float2(cscale * acc[nt][0], cscale * acc[nt][1]);
        *(float2*)(ts + (size_t)gb1 * 128 + col) = make_float2(cscale * acc[nt][2], cscale * acc[nt][3]);
    }
}

// ============ Kernel V: 32-row CTA, 256 thr, 2 CTAs/SM ============
template <int M>
__global__ __launch_bounds__(256, 2)
void tp_v_kernel(const float* __restrict__ s1, const float* __restrict__ v1,
                 const float* __restrict__ s2, const float* __restrict__ v2,
                 const uint32_t* __restrict__ wv, float* __restrict__ tv, float cscale) {
    extern __shared__ uint32_t dsm[];       // Wbuf 2*8448 | afrag 8*NKT*128
    constexpr int NKT = M / 16, NCHK = M / 32, NCT = M * NCHK;
    constexpr int PSTR = M * M * 128;
    uint32_t* afrag = dsm + 16896;
    const uint32_t smem_base = smem_u32(dsm);
    const int tid = threadIdx.x, wid = tid >> 5, lane = tid & 31;
    const int rq = wid >> 2, ng = wid & 3;            // rq in {0,1}
    const int g = lane >> 2, t4 = lane & 3;
    const int bb = blockIdx.x * 32;
    const int gb0 = bb + rq * 16 + g, gb1 = gb0 + 8;

    float Tsv[4][4], Tvs[4][4], dv[3][4][4];
#pragma unroll
    for (int nt = 0; nt < 4; ++nt)
#pragma unroll
        for (int j = 0; j < 4; ++j) {
            Tsv[nt][j] = 0.f; Tvs[nt][j] = 0.f;
            dv[0][nt][j] = 0.f; dv[1][nt][j] = 0.f; dv[2][nt][j] = 0.f;
        }

    auto docopy = [&](int ci, int b) {
        const uint32_t sb0 = smem_base + (uint32_t)(b * 8448) * 4;
#pragma unroll
        for (int i = 0; i < 8; ++i) {
            int sg = tid + 256 * i;                 // 0..2047
            int c = sg & 31, kp = (sg >> 5) & 15, h = (sg >> 9) & 1, s = sg >> 10;
            const uint32_t* src = wv + (size_t)s * PSTR + (size_t)ci * 4096 + h * 2048 + kp * 128 + c * 4;
            CP_ASYNC16(sb0 + (uint32_t)((((s * 2 + h) * 16 + kp) * 132 + c * 4) * 4), src);
        }
    };

    docopy(0, 0);
    CP_COMMIT();

    // A fragments: idx = (((s*2+h)*2 + rr)*NKT + kt)*128 + ln*4
    for (int it = tid; it < 2 * 2 * NKT * 32; it += 256) {
        int ln = it & 31;
        int kt = (it >> 5) % NKT;
        int rr = ((it >> 5) / NKT) % 2;
        int s  = (it >> 5) / (NKT * 2);
        const float* src = s ? s2 : s1;
        int r0 = bb + rr * 16 + (ln >> 2);
        int kp0 = kt * 8 + (ln & 3);
        uint32_t h[4], l[4];
        float2 x;
        x = *(const float2*)(src + (size_t)r0 * M + 2 * kp0);             split_pack(x.x, x.y, h[0], l[0]);
        x = *(const float2*)(src + (size_t)(r0 + 8) * M + 2 * kp0);       split_pack(x.x, x.y, h[1], l[1]);
        x = *(const float2*)(src + (size_t)r0 * M + 2 * (kp0 + 4));       split_pack(x.x, x.y, h[2], l[2]);
        x = *(const float2*)(src + (size_t)(r0 + 8) * M + 2 * (kp0 + 4)); split_pack(x.x, x.y, h[3], l[3]);
        uint32_t* ah = afrag + (((size_t)((s * 2 + 0) * 2) + rr) * NKT + kt) * 128 + ln * 4;
        uint32_t* al = afrag + (((size_t)((s * 2 + 1) * 2) + rr) * NKT + kt) * 128 + ln * 4;
        *(uint4*)ah = make_uint4(h[0], h[1], h[2], h[3]);
        *(uint4*)al = make_uint4(l[0], l[1], l[2], l[3]);
    }
    __syncthreads();

    int m = 0, c = 0;
    for (int ci = 0; ci < NCT; ++ci) {
        const int cur = ci & 1;
        if (ci + 1 < NCT) { docopy(ci + 1, cur ^ 1); CP_COMMIT(); CP_WAIT1(); }
        else CP_WAIT0();
        __syncthreads();

        const uint32_t* bufb = dsm + cur * 8448;
        const int boff = g * 16 + ng * 4;
#pragma unroll
        for (int j = 0; j < 2; ++j) {
            const int kt = c * 2 + j;
            uint4 Ah = *(const uint4*)(afrag + (((size_t)(0 * 2) + rq) * NKT + kt) * 128 + lane * 4);
            uint4 Al = *(const uint4*)(afrag + (((size_t)(1 * 2) + rq) * NKT + kt) * 128 + lane * 4);
            uint4 Ch = *(const uint4*)(afrag + (((size_t)(2 * 2) + rq) * NKT + kt) * 128 + lane * 4);
            uint4 Cl = *(const uint4*)(afrag + (((size_t)(3 * 2) + rq) * NKT + kt) * 128 + lane * 4);
            const uint32_t* b0h = bufb + (0 * 16 + j * 8 + t4) * 132 + boff;
            const uint32_t* b1h = bufb + (0 * 16 + j * 8 + 4 + t4) * 132 + boff;
            uint4 BH0 = *(const uint4*)b0h, BH1 = *(const uint4*)b1h;
            uint4 BL0 = *(const uint4*)(b0h + 16 * 132), BL1 = *(const uint4*)(b1h + 16 * 132);
            const uint32_t* d0h = bufb + (2 * 16 + j * 8 + t4) * 132 + boff;
            const uint32_t* d1h = bufb + (2 * 16 + j * 8 + 4 + t4) * 132 + boff;
            uint4 DH0 = *(const uint4*)d0h, DH1 = *(const uint4*)d1h;
            uint4 DL0 = *(const uint4*)(d0h + 16 * 132), DL1 = *(const uint4*)(d1h + 16 * 132);
            uint32_t bh0[4]={BH0.x,BH0.y,BH0.z,BH0.w}, bh1[4]={BH1.x,BH1.y,BH1.z,BH1.w};
            uint32_t bl0[4]={BL0.x,BL0.y,BL0.z,BL0.w}, bl1[4]={BL1.x,BL1.y,BL1.z,BL1.w};
            uint32_t dh0[4]={DH0.x,DH0.y,DH0.z,DH0.w}, dh1[4]={DH1.x,DH1.y,DH1.z,DH1.w};
            uint32_t dl0[4]={DL0.x,DL0.y,DL0.z,DL0.w}, dl1[4]={DL1.x,DL1.y,DL1.z,DL1.w};
#pragma unroll
            for (int nt = 0; nt < 4; ++nt) {
                MMA_BF16(Tsv[nt], Ah.x, Ah.y, Ah.z, Ah.w, bh0[nt], bh1[nt]);
                MMA_BF16(Tsv[nt], Al.x, Al.y, Al.z, Al.w, bh0[nt], bh1[nt]);
                MMA_BF16(Tsv[nt], Ah.x, Ah.y, Ah.z, Ah.w, bl0[nt], bl1[nt]);
                MMA_BF16(Tvs[nt], Ch.x, Ch.y, Ch.z, Ch.w, dh0[nt], dh1[nt]);
                MMA_BF16(Tvs[nt], Cl.x, Cl.y, Cl.z, Cl.w, dh0[nt], dh1[nt]);
                MMA_BF16(Tvs[nt], Ch.x, Ch.y, Ch.z, Ch.w, dl0[nt], dl1[nt]);
            }
        }

        if (c == NCHK - 1) {
            float sv0[3], sv1[3], vs0[3], vs1[3];
#pragma unroll
            for (int i = 0; i < 3; ++i) {
                sv0[i] = __ldg(v2 + (size_t)i * PLANE + (size_t)gb0 * M + m);
                sv1[i] = __ldg(v2 + (size_t)i * PLANE + (size_t)gb1 * M + m);
                vs0[i] = __ldg(v1 + (size_t)i * PLANE + (size_t)gb0 * M + m);
                vs1[i] = __ldg(v1 + (size_t)i * PLANE + (size_t)gb1 * M + m);
            }
#pragma unroll
            for (int i = 0; i < 3; ++i)
#pragma unroll
                for (int nt = 0; nt < 4; ++nt) {
                    dv[i][nt][0] += sv0[i] * Tsv[nt][0] + vs0[i] * Tvs[nt][0];
                    dv[i][nt][1] += sv0[i] * Tsv[nt][1] + vs0[i] * Tvs[nt][1];
                    dv[i][nt][2] += sv1[i] * Tsv[nt][2] + vs1[i] * Tvs[nt][2];
                    dv[i][nt][3] += sv1[i] * Tsv[nt][3] + vs1[i] * Tvs[nt][3];
                }
#pragma unroll
            for (int nt = 0; nt < 4; ++nt)
#pragma unroll
                for (int j2 = 0; j2 < 4; ++j2) { Tsv[nt][j2] = 0.f; Tvs[nt][j2] = 0.f; }
            ++m; c = 0;
        } else ++c;
        __syncthreads();
    }

#pragma unroll
    for (int i = 0; i < 3; ++i) {
        float* op = tv + (size_t)i * PLANE;
#pragma unroll
        for (int nt = 0; nt < 4; ++nt) {
            const int col = ng * 32 + nt * 8 + 2 * t4;
            *(float2*)(op + (size_t)gb0 * 128 + col) = make_float2(cscale * dv[i][nt][0], cscale * dv[i][nt][1]);
            *(float2*)(op + (size_t)gb1 * 128 + col) = make_float2(cscale * dv[i][nt][2], cscale * dv[i][nt][3]);
        }
    }
}

// ============ split / pack / gemm / gate ============
__global__ void split_kernel(const float* __restrict__ x,
                             float* __restrict__ s, float* __restrict__ v) {
    int i = blockIdx.x * 256 + threadIdx.x;
    if (i >= BATCH * 64) return;
    int b = i >> 6, u = i & 63;
    const float* xr = x + b * 256;
    s[i] = xr[u];
    v[0 * PLANE + i] = xr[64 + 3 * u + 0];
    v[1 * PLANE + i] = xr[64 + 3 * u + 1];
    v[2 * PLANE + i] = xr[64 + 3 * u + 2];
}
__global__ void pack_kernel(const float* __restrict__ s,
                            const float* __restrict__ v, float* __restrict__ out) {
    int i = blockIdx.x * 256 + threadIdx.x;
    if (i >= BATCH * 64) return;
    int b = i >> 6, u = i & 63;
    float* orow = out + b * 256;
    orow[u] = s[i];
    orow[64 + 3 * u + 0] = v[0 * PLANE + i];
    orow[64 + 3 * u + 1] = v[1 * PLANE + i];
    orow[64 + 3 * u + 2] = v[2 * PLANE + i];
}
template <int NC>
__global__ __launch_bounds__(256)
void gemm_kernel(const float* __restrict__ X, const float* __restrict__ Wm,
                 float* __restrict__ Y, int K, float scale) {
    constexpr int N = 32 * NC;
    X += (size_t)blockIdx.y * PLANE;
    Y += (size_t)blockIdx.y * PLANE;
    __shared__ float Xs[32][33];
    __shared__ float Ws[32][N + 1];
    const int tx = threadIdx.x, ty = threadIdx.y;
    const int tid = ty * 32 + tx;
    const int row0 = blockIdx.x * 32;
    float acc[4][NC];
#pragma unroll
    for (int r = 0; r < 4; ++r)
#pragma unroll
        for (int j = 0; j < NC; ++j) acc[r][j] = 0.f;
    for (int k0 = 0; k0 < K; k0 += 32) {
#pragma unroll
        for (int e = tid; e < 32 * 32; e += 256) {
            int r = e >> 5, kk = e & 31;
            Xs[r][kk] = X[(size_t)(row0 + r) * K + k0 + kk];
        }
        for (int e = tid; e < 32 * N; e += 256) {
            int kk = e / N, n = e - kk * N;
            Ws[kk][n] = Wm[(size_t)(k0 + kk) * N + n];
        }
        __syncthreads();
#pragma unroll 8
        for (int kk = 0; kk < 32; ++kk) {
            float wvv[NC];
#pragma unroll
            for (int j = 0; j < NC; ++j) wvv[j] = Ws[kk][tx * NC + j];
#pragma unroll
            for (int r = 0; r < 4; ++r) {
                float xv = Xs[ty * 4 + r][kk];
#pragma unroll
                for (int j = 0; j < NC; ++j) acc[r][j] += xv * wvv[j];
            }
        }
        __syncthreads();
    }
#pragma unroll
    for (int r = 0; r < 4; ++r)
#pragma unroll
        for (int j = 0; j < NC; ++j)
            Y[(size_t)(row0 + ty * 4 + r) * N + tx * NC + j] = scale * acc[r][j];
}
__global__ void gate_kernel(const float* __restrict__ sl, const float* __restrict__ g,
                            const float* __restrict__ vl,
                            float* __restrict__ gs, float* __restrict__ gv) {
    int i = blockIdx.x * 256 + threadIdx.x;
    if (i >= BATCH * 128) return;
    gs[i] = GAIN * tanhf(sl[i]);
    float t = GAIN * tanhf(g[i]);
    gv[0 * PLANE + i] = t * vl[0 * PLANE + i];
    gv[1 * PLANE + i] = t * vl[1 * PLANE + i];
    gv[2 * PLANE + i] = t * vl[2 * PLANE + i];
}

static inline void run_gemm(const float* X, const float* W, float* Y,
                            int K, int N, float scale, int planes) {
    dim3 blk(32, 8), grd(BATCH / 32, planes);
    if (N == 64) gemm_kernel<2><<<grd, blk>>>(X, W, Y, K, scale);
    else         gemm_kernel<4><<<grd, blk>>>(X, W, Y, K, scale);
}

extern "C" void kernel_launch(void* const* d_in, const int* in_sizes, int n_in,
                              void* d_out, int out_size) {
    const float* in[29];
    for (int i = 0; i < 29; ++i) in[i] = (const float*)d_in[i];
    float* out = (float*)d_out;

    float *s, *v, *s1, *v1, *s2, *v2, *ts, *tv;
    uint32_t *wp1, *wp2, *wv1, *wv2;
    cudaGetSymbolAddress((void**)&s,  g_s);
    cudaGetSymbolAddress((void**)&v,  g_v);
    cudaGetSymbolAddress((void**)&s1, g_s1);
    cudaGetSymbolAddress((void**)&v1, g_v1);
    cudaGetSymbolAddress((void**)&s2, g_s2);
    cudaGetSymbolAddress((void**)&v2, g_v2);
    cudaGetSymbolAddress((void**)&ts, g_ts);
    cudaGetSymbolAddress((void**)&tv, g_tv);
    cudaGetSymbolAddress((void**)&wp1, g_wp1);
    cudaGetSymbolAddress((void**)&wp2, g_wp2);
    cudaGetSymbolAddress((void**)&wv1, g_wv1);
    cudaGetSymbolAddress((void**)&wv2, g_wv2);

    const int P_SMEM  = 2 * 4224 * 4;                       // 33792
    const int V_SMEM1 = (16896 + 4096) * 4;                 // 83968
    const int V_SMEM2 = (16896 + 8192) * 4;                 // 100352
    cudaFuncSetAttribute(tp_p_kernel<64>,  cudaFuncAttributeMaxDynamicSharedMemorySize, P_SMEM);
    cudaFuncSetAttribute(tp_p_kernel<128>, cudaFuncAttributeMaxDynamicSharedMemorySize, P_SMEM);
    cudaFuncSetAttribute(tp_v_kernel<64>,  cudaFuncAttributeMaxDynamicSharedMemorySize, V_SMEM1);
    cudaFuncSetAttribute(tp_v_kernel<128>, cudaFuncAttributeMaxDynamicSharedMemorySize, V_SMEM2);

    const float c64  = 0.125f;
    const float c128 = 0.08838834764831845f;
    const float ctp1 = 1.0f / (64.0f  * 1.4142135623730951f);
    const float ctp2 = 1.0f / (128.0f * 1.4142135623730951f);

    // prepass
    {
        const int t1 = (64 * 64 / 2) * 128, t2 = (128 * 128 / 2) * 128;
        const int p1 = 64 * 64 * 128, p2 = 128 * 128 * 128;
        pack_weights_kernel<<<(t1 + 255) / 256, 256>>>(in[5], wp1, 64);
        pack_weights_kernel<<<(t1 + 255) / 256, 256>>>(in[6], wp1 + p1, 64);
        pack_weights_v_kernel<<<(t1 + 255) / 256, 256>>>(in[7], wv1, 64, 1);
        pack_weights_v_kernel<<<(t1 + 255) / 256, 256>>>(in[8], wv1 + p1, 64, 0);
        pack_weights_kernel<<<(t2 + 255) / 256, 256>>>(in[18], wp2, 128);
        pack_weights_kernel<<<(t2 + 255) / 256, 256>>>(in[19], wp2 + p2, 128);
        pack_weights_v_kernel<<<(t2 + 255) / 256, 256>>>(in[20], wv2, 128, 1);
        pack_weights_v_kernel<<<(t2 + 255) / 256, 256>>>(in[21], wv2 + p2, 128, 0);
    }

    split_kernel<<<BATCH * 64 / 256, 256>>>(in[0], s, v);

    // block 1
    run_gemm(s, in[1], s1, 64, 64, c64, 1);
    run_gemm(v, in[2], v1, 64, 64, c64, 3);
    run_gemm(s, in[3], s2, 64, 64, c64, 1);
    run_gemm(v, in[4], v2, 64, 64, c64, 3);
    tp_p_kernel<64><<<BATCH / 32, 256, P_SMEM>>>(s1, v1, s2, v2, wp1, ts, ctp1);
    tp_v_kernel<64><<<BATCH / 32, 256, V_SMEM1>>>(s1, v1, s2, v2, wv1, tv, ctp1);
    run_gemm(ts, in[9],  s1, 128, 128, c128, 1);
    run_gemm(ts, in[10], s2, 128, 128, c128, 1);
    run_gemm(tv, in[11], v1, 128, 128, c128, 3);
    gate_kernel<<<BATCH * 128 / 256, 256>>>(s1, s2, v1, ts, tv);
    run_gemm(ts, in[12], s, 128, 128, c128, 1);
    run_gemm(tv, in[13], v, 128, 128, c128, 3);

    // block 2
    run_gemm(s, in[14], s1, 128, 128, c128, 1);
    run_gemm(v, in[15], v1, 128, 128, c128, 3);
    run_gemm(s, in[16], s2, 128, 128, c128, 1);
    run_gemm(v, in[17], v2, 128, 128, c128, 3);
    tp_p_kernel<128><<<BATCH / 32, 256, P_SMEM>>>(s1, v1, s2, v2, wp2, ts, ctp2);
    tp_v_kernel<128><<<BATCH / 32, 256, V_SMEM2>>>(s1, v1, s2, v2, wv2, tv, ctp2);
    run_gemm(ts, in[22], s1, 128, 128, c128, 1);
    run_gemm(ts, in[23], s2, 128, 128, c128, 1);
    run_gemm(tv, in[24], v1, 128, 128, c128, 3);
    gate_kernel<<<BATCH * 128 / 256, 256>>>(s1, s2, v1, ts, tv);
    run_gemm(ts, in[25], s, 128, 128, c128, 1);
    run_gemm(tv, in[26], v, 128, 128, c128, 3);

    // final
    run_gemm(s, in[27], s1, 128, 64, c128, 1);
    run_gemm(v, in[28], v1, 128, 64, c128, 3);
    pack_kernel<<<BATCH * 64 / 256, 256>>>(s1, v1, out);
}

// round 9
// speedup vs baseline: 2.2210x; 1.0614x over previous
#include <cuda_runtime.h>
#include <cstdint>
#include <math.h>

#define BATCH 8192
#define PLANE (8192 * 128)
#define GAIN 1.5927116870880127f
#define INV_SQRT3 0.57735026918962576f

__device__ float g_s [PLANE];
__device__ float g_v [3 * PLANE];
__device__ float g_s1[PLANE];
__device__ float g_v1[3 * PLANE];
__device__ float g_s2[PLANE];
__device__ float g_v2[3 * PLANE];
__device__ float g_ts[PLANE];
__device__ float g_tv[3 * PLANE];
__device__ uint32_t g_wp1[2u * 64 * 64 * 128];
__device__ uint32_t g_wp2[2u * 128 * 128 * 128];
__device__ uint32_t g_wv1[2u * 64 * 64 * 128];
__device__ uint32_t g_wv2[2u * 128 * 128 * 128];

__device__ __forceinline__ uint32_t smem_u32(const void* p) {
    uint32_t a;
    asm("{ .reg .u64 t; cvta.to.shared.u64 t, %1; cvt.u32.u64 %0, t; }" : "=r"(a) : "l"(p));
    return a;
}
#define MMA_BF16(d, a0, a1, a2, a3, b0, b1)                                 \
    asm volatile(                                                           \
        "mma.sync.aligned.m16n8k16.row.col.f32.bf16.bf16.f32 "              \
        "{%0,%1,%2,%3}, {%4,%5,%6,%7}, {%8,%9}, {%0,%1,%2,%3};"             \
        : "+f"((d)[0]), "+f"((d)[1]), "+f"((d)[2]), "+f"((d)[3])            \
        : "r"(a0), "r"(a1), "r"(a2), "r"(a3), "r"(b0), "r"(b1))
#define CP_ASYNC16(sa, gp) \
    asm volatile("cp.async.ca.shared.global [%0], [%1], 16;" :: "r"(sa), "l"(gp) : "memory")
#define CP_COMMIT() asm volatile("cp.async.commit_group;" ::: "memory")
#define CP_WAIT2()  asm volatile("cp.async.wait_group 2;" ::: "memory")
#define CP_WAIT1()  asm volatile("cp.async.wait_group 1;" ::: "memory")
#define CP_WAIT0()  asm volatile("cp.async.wait_group 0;" ::: "memory")

__device__ __forceinline__ void split_pack(float x0, float x1,
                                           uint32_t& hi, uint32_t& lo) {
    uint32_t h;
    asm("cvt.rn.bf16x2.f32 %0, %1, %2;" : "=r"(h) : "f"(x1), "f"(x0));
    float l0 = x0 - __uint_as_float(h << 16);
    float l1 = x1 - __uint_as_float(h & 0xFFFF0000u);
    asm("cvt.rn.bf16x2.f32 %0, %1, %2;" : "=r"(lo) : "f"(l1), "f"(l0));
    hi = h;
}

// P-form prepass
__global__ void pack_weights_kernel(const float* __restrict__ w,
                                    uint32_t* __restrict__ dst, int M) {
    int idx = blockIdx.x * 256 + threadIdx.x;
    if (idx >= (M * M / 2) * 128) return;
    int kpair = idx >> 7, n = idx & 127;
    int u = kpair / (M / 2), rem = kpair % (M / 2);
    int vw = rem >> 3, kp = rem & 7;
    int v = vw * 16 + 2 * kp;
    uint32_t hi, lo;
    split_pack(w[((size_t)u * M + v) * 128 + n], w[((size_t)u * M + v + 1) * 128 + n], hi, lo);
    int np = (n & 7) * 16 + (n >> 3);
    size_t base = ((size_t)(vw * M + u)) * 2048;
    dst[base + kp * 128 + np] = hi;
    dst[base + 1024 + kp * 128 + np] = lo;
}
// V-form prepass
__global__ void pack_weights_v_kernel(const float* __restrict__ w,
                                      uint32_t* __restrict__ dst, int M, int transpose) {
    int idx = blockIdx.x * 256 + threadIdx.x;
    if (idx >= (M * M / 2) * 128) return;
    int gkp = idx >> 7, n = idx & 127;
    int m = gkp / (M / 2), kp_g = gkp % (M / 2);
    int kh = kp_g >> 4, kp = kp_g & 15;
    int k0 = 2 * kp_g;
    float x0, x1;
    if (transpose) { x0 = w[((size_t)k0 * M + m) * 128 + n]; x1 = w[((size_t)(k0 + 1) * M + m) * 128 + n]; }
    else           { x0 = w[((size_t)m * M + k0) * 128 + n]; x1 = w[((size_t)m * M + k0 + 1) * 128 + n]; }
    uint32_t hi, lo;
    split_pack(x0, x1, hi, lo);
    int np = (n & 7) * 16 + (n >> 3);
    size_t base = ((size_t)(m * (M / 32) + kh)) * 4096;
    dst[base + (size_t)kp * 128 + np] = hi;
    dst[base + 2048 + (size_t)kp * 128 + np] = lo;
}

// ============ Kernel P: 32-row CTA, 4-stage ring, ONE barrier/step ============
template <int M>
__global__ __launch_bounds__(256, 2)
void tp_p_kernel(const float* __restrict__ s1, const float* __restrict__ v1,
                 const float* __restrict__ s2, const float* __restrict__ v2,
                 const uint32_t* __restrict__ wp, float* __restrict__ ts, float cscale) {
    extern __shared__ uint32_t dsm[];                 // 4*4224 words
    constexpr int PSTR = M * M * 128;
    const uint32_t smem_base = smem_u32(dsm);
    const int tid = threadIdx.x, wid = tid >> 5, lane = tid & 31;
    const int rq = wid >> 2, ng = wid & 3;
    const int g = lane >> 2, t4 = lane & 3;
    const int bb = blockIdx.x * 32;
    const int gb0 = bb + rq * 16 + g, gb1 = gb0 + 8;

    float acc[4][4];
#pragma unroll
    for (int nt = 0; nt < 4; ++nt)
#pragma unroll
        for (int j = 0; j < 4; ++j) acc[nt][j] = 0.f;

    const float* s1r0 = s1 + (size_t)gb0 * M;
    const float* s1r1 = s1 + (size_t)gb1 * M;
    const float* s2r0 = s2 + (size_t)gb0 * M;
    const float* s2r1 = s2 + (size_t)gb1 * M;
    const float *v1r0[3], *v1r1[3], *v2r0[3], *v2r1[3];
#pragma unroll
    for (int i = 0; i < 3; ++i) {
        v1r0[i] = v1 + (size_t)i * PLANE + (size_t)gb0 * M;
        v1r1[i] = v1 + (size_t)i * PLANE + (size_t)gb1 * M;
        v2r0[i] = v2 + (size_t)i * PLANE + (size_t)gb0 * M;
        v2r1[i] = v2 + (size_t)i * PLANE + (size_t)gb1 * M;
    }

    auto docopy = [&](int blk, int b) {
        const uint32_t sb0 = smem_base + (uint32_t)(b * 4224) * 4;
#pragma unroll
        for (int i = 0; i < 4; ++i) {
            int sg = tid + 256 * i;                 // 0..1023
            int c = sg & 31, kp = (sg >> 5) & 7, h = (sg >> 8) & 1, pl = sg >> 9;
            const uint32_t* src = wp + (size_t)pl * PSTR + (size_t)blk * 2048 + h * 1024 + kp * 128 + c * 4;
            CP_ASYNC16(sb0 + (uint32_t)((((pl * 2 + h) * 8 + kp) * 132 + c * 4) * 4), src);
        }
    };

    for (int vw = 0; vw < M / 16; ++vw) {
        const int v0w = vw * 16;
        // a2 operands: loop-invariant in u
        const int ca = v0w + 2 * t4, cb = ca + 8;
        float s2v[2][4], v2v[3][2][4];
        {
            float2 A, B;
            A = __ldg((const float2*)(s2r0 + ca)); B = __ldg((const float2*)(s2r0 + cb));
            s2v[0][0]=A.x; s2v[0][1]=A.y; s2v[0][2]=B.x; s2v[0][3]=B.y;
            A = __ldg((const float2*)(s2r1 + ca)); B = __ldg((const float2*)(s2r1 + cb));
            s2v[1][0]=A.x; s2v[1][1]=A.y; s2v[1][2]=B.x; s2v[1][3]=B.y;
#pragma unroll
            for (int i = 0; i < 3; ++i) {
                A = __ldg((const float2*)(v2r0[i] + ca)); B = __ldg((const float2*)(v2r0[i] + cb));
                v2v[i][0][0]=A.x; v2v[i][0][1]=A.y; v2v[i][0][2]=B.x; v2v[i][0][3]=B.y;
                A = __ldg((const float2*)(v2r1[i] + ca)); B = __ldg((const float2*)(v2r1[i] + cb));
                v2v[i][1][0]=A.x; v2v[i][1][1]=A.y; v2v[i][1][2]=B.x; v2v[i][1][3]=B.y;
            }
        }

        docopy(vw * M + 0, 0); CP_COMMIT();
        docopy(vw * M + 1, 1); CP_COMMIT();

        for (int u = 0; u < M; ++u) {
            if (u + 2 < M) { docopy(vw * M + u + 2, (u + 2) & 3); CP_COMMIT(); CP_WAIT2(); }
            else if (u + 1 < M) CP_WAIT1();
            else CP_WAIT0();
            __syncthreads();    // buf[u&3] visible; also read-guard (4-ring proof)

            float s1a[2], v1a[3][2];
            s1a[0] = __ldg(s1r0 + u); s1a[1] = __ldg(s1r1 + u);
#pragma unroll
            for (int i = 0; i < 3; ++i) { v1a[i][0] = __ldg(v1r0[i] + u); v1a[i][1] = __ldg(v1r1[i] + u); }

            float pav[2][4], pbv[2][4];
#pragma unroll
            for (int r = 0; r < 2; ++r)
#pragma unroll
                for (int j = 0; j < 4; ++j) {
                    pav[r][j] = s1a[r] * s2v[r][j];
                    pbv[r][j] = INV_SQRT3 * (v1a[0][r] * v2v[0][r][j] +
                                             v1a[1][r] * v2v[1][r][j] +
                                             v1a[2][r] * v2v[2][r][j]);
                }
            const uint32_t* bufb = dsm + (u & 3) * 4224;
            const int boff = g * 16 + ng * 4;
#pragma unroll
            for (int st = 0; st < 2; ++st) {
                float (*pv)[4] = st ? pbv : pav;
                uint32_t fh[4], fl[4];
                split_pack(pv[0][0], pv[0][1], fh[0], fl[0]);
                split_pack(pv[1][0], pv[1][1], fh[1], fl[1]);
                split_pack(pv[0][2], pv[0][3], fh[2], fl[2]);
                split_pack(pv[1][2], pv[1][3], fh[3], fl[3]);
                const uint32_t* h0p = bufb + ((st * 2) * 8 + t4) * 132 + boff;
                const uint32_t* h1p = bufb + ((st * 2) * 8 + t4 + 4) * 132 + boff;
                uint4 H0 = *(const uint4*)h0p, H1 = *(const uint4*)h1p;
                uint4 L0 = *(const uint4*)(h0p + 8 * 132), L1 = *(const uint4*)(h1p + 8 * 132);
                uint32_t h0a[4]={H0.x,H0.y,H0.z,H0.w}, h1a[4]={H1.x,H1.y,H1.z,H1.w};
                uint32_t l0a[4]={L0.x,L0.y,L0.z,L0.w}, l1a[4]={L1.x,L1.y,L1.z,L1.w};
#pragma unroll
                for (int j = 0; j < 4; ++j) {
                    float* d = acc[j];
                    MMA_BF16(d, fh[0], fh[1], fh[2], fh[3], h0a[j], h1a[j]);
                    MMA_BF16(d, fl[0], fl[1], fl[2], fl[3], h0a[j], h1a[j]);
                    MMA_BF16(d, fh[0], fh[1], fh[2], fh[3], l0a[j], l1a[j]);
                }
            }
        }
        __syncthreads();   // window boundary: old-window reads done before ring restart
    }
#pragma unroll
    for (int nt = 0; nt < 4; ++nt) {
        const int col = ng * 32 + nt * 8 + 2 * t4;
        *(float2*)(ts + (size_t)gb0 * 128 + col) = make_float2(cscale * acc[nt][0], cscale * acc[nt][1]);
        *(float2*)(ts + (size_t)gb1 * 128 + col) = make_float2(cscale * acc[nt][2], cscale * acc[nt][3]);
    }
}

// ============ Kernel V: unchanged machinery (2-buf) ============
template <int M>
__global__ __launch_bounds__(256, 2)
void tp_v_kernel(const float* __restrict__ s1, const float* __restrict__ v1,
                 const float* __restrict__ s2, const float* __restrict__ v2,
                 const uint32_t* __restrict__ wv, float* __restrict__ tv, float cscale) {
    extern __shared__ uint32_t dsm[];
    constexpr int NKT = M / 16, NCHK = M / 32, NCT = M * NCHK;
    constexpr int PSTR = M * M * 128;
    uint32_t* afrag = dsm + 16896;
    const uint32_t smem_base = smem_u32(dsm);
    const int tid = threadIdx.x, wid = tid >> 5, lane = tid & 31;
    const int rq = wid >> 2, ng = wid & 3;
    const int g = lane >> 2, t4 = lane & 3;
    const int bb = blockIdx.x * 32;
    const int gb0 = bb + rq * 16 + g, gb1 = gb0 + 8;

    float Tsv[4][4], Tvs[4][4], dv[3][4][4];
#pragma unroll
    for (int nt = 0; nt < 4; ++nt)
#pragma unroll
        for (int j = 0; j < 4; ++j) {
            Tsv[nt][j] = 0.f; Tvs[nt][j] = 0.f;
            dv[0][nt][j] = 0.f; dv[1][nt][j] = 0.f; dv[2][nt][j] = 0.f;
        }

    auto docopy = [&](int ci, int b) {
        const uint32_t sb0 = smem_base + (uint32_t)(b * 8448) * 4;
#pragma unroll
        for (int i = 0; i < 8; ++i) {
            int sg = tid + 256 * i;
            int c = sg & 31, kp = (sg >> 5) & 15, h = (sg >> 9) & 1, s = sg >> 10;
            const uint32_t* src = wv + (size_t)s * PSTR + (size_t)ci * 4096 + h * 2048 + kp * 128 + c * 4;
            CP_ASYNC16(sb0 + (uint32_t)((((s * 2 + h) * 16 + kp) * 132 + c * 4) * 4), src);
        }
    };

    docopy(0, 0);
    CP_COMMIT();

    for (int it = tid; it < 2 * 2 * NKT * 32; it += 256) {
        int ln = it & 31;
        int kt = (it >> 5) % NKT;
        int rr = ((it >> 5) / NKT) % 2;
        int s  = (it >> 5) / (NKT * 2);
        const float* src = s ? s2 : s1;
        int r0 = bb + rr * 16 + (ln >> 2);
        int kp0 = kt * 8 + (ln & 3);
        uint32_t h[4], l[4];
        float2 x;
        x = *(const float2*)(src + (size_t)r0 * M + 2 * kp0);             split_pack(x.x, x.y, h[0], l[0]);
        x = *(const float2*)(src + (size_t)(r0 + 8) * M + 2 * kp0);       split_pack(x.x, x.y, h[1], l[1]);
        x = *(const float2*)(src + (size_t)r0 * M + 2 * (kp0 + 4));       split_pack(x.x, x.y, h[2], l[2]);
        x = *(const float2*)(src + (size_t)(r0 + 8) * M + 2 * (kp0 + 4)); split_pack(x.x, x.y, h[3], l[3]);
        uint32_t* ah = afrag + (((size_t)((s * 2 + 0) * 2) + rr) * NKT + kt) * 128 + ln * 4;
        uint32_t* al = afrag + (((size_t)((s * 2 + 1) * 2) + rr) * NKT + kt) * 128 + ln * 4;
        *(uint4*)ah = make_uint4(h[0], h[1], h[2], h[3]);
        *(uint4*)al = make_uint4(l[0], l[1], l[2], l[3]);
    }
    __syncthreads();

    int m = 0, c = 0;
    for (int ci = 0; ci < NCT; ++ci) {
        const int cur = ci & 1;
        if (ci + 1 < NCT) { docopy(ci + 1, cur ^ 1); CP_COMMIT(); CP_WAIT1(); }
        else CP_WAIT0();
        __syncthreads();

        const uint32_t* bufb = dsm + cur * 8448;
        const int boff = g * 16 + ng * 4;
#pragma unroll
        for (int j = 0; j < 2; ++j) {
            const int kt = c * 2 + j;
            uint4 Ah = *(const uint4*)(afrag + (((size_t)(0 * 2) + rq) * NKT + kt) * 128 + lane * 4);
            uint4 Al = *(const uint4*)(afrag + (((size_t)(1 * 2) + rq) * NKT + kt) * 128 + lane * 4);
            uint4 Ch = *(const uint4*)(afrag + (((size_t)(2 * 2) + rq) * NKT + kt) * 128 + lane * 4);
            uint4 Cl = *(const uint4*)(afrag + (((size_t)(3 * 2) + rq) * NKT + kt) * 128 + lane * 4);
            const uint32_t* b0h = bufb + (0 * 16 + j * 8 + t4) * 132 + boff;
            const uint32_t* b1h = bufb + (0 * 16 + j * 8 + 4 + t4) * 132 + boff;
            uint4 BH0 = *(const uint4*)b0h, BH1 = *(const uint4*)b1h;
            uint4 BL0 = *(const uint4*)(b0h + 16 * 132), BL1 = *(const uint4*)(b1h + 16 * 132);
            const uint32_t* d0h = bufb + (2 * 16 + j * 8 + t4) * 132 + boff;
            const uint32_t* d1h = bufb + (2 * 16 + j * 8 + 4 + t4) * 132 + boff;
            uint4 DH0 = *(const uint4*)d0h, DH1 = *(const uint4*)d1h;
            uint4 DL0 = *(const uint4*)(d0h + 16 * 132), DL1 = *(const uint4*)(d1h + 16 * 132);
            uint32_t bh0[4]={BH0.x,BH0.y,BH0.z,BH0.w}, bh1[4]={BH1.x,BH1.y,BH1.z,BH1.w};
            uint32_t bl0[4]={BL0.x,BL0.y,BL0.z,BL0.w}, bl1[4]={BL1.x,BL1.y,BL1.z,BL1.w};
            uint32_t dh0[4]={DH0.x,DH0.y,DH0.z,DH0.w}, dh1[4]={DH1.x,DH1.y,DH1.z,DH1.w};
            uint32_t dl0[4]={DL0.x,DL0.y,DL0.z,DL0.w}, dl1[4]={DL1.x,DL1.y,DL1.z,DL1.w};
#pragma unroll
            for (int nt = 0; nt < 4; ++nt) {
                MMA_BF16(Tsv[nt], Ah.x, Ah.y, Ah.z, Ah.w, bh0[nt], bh1[nt]);
                MMA_BF16(Tsv[nt], Al.x, Al.y, Al.z, Al.w, bh0[nt], bh1[nt]);
                MMA_BF16(Tsv[nt], Ah.x, Ah.y, Ah.z, Ah.w, bl0[nt], bl1[nt]);
                MMA_BF16(Tvs[nt], Ch.x, Ch.y, Ch.z, Ch.w, dh0[nt], dh1[nt]);
                MMA_BF16(Tvs[nt], Cl.x, Cl.y, Cl.z, Cl.w, dh0[nt], dh1[nt]);
                MMA_BF16(Tvs[nt], Ch.x, Ch.y, Ch.z, Ch.w, dl0[nt], dl1[nt]);
            }
        }

        if (c == NCHK - 1) {
            float sv0[3], sv1[3], vs0[3], vs1[3];
#pragma unroll
            for (int i = 0; i < 3; ++i) {
                sv0[i] = __ldg(v2 + (size_t)i * PLANE + (size_t)gb0 * M + m);
                sv1[i] = __ldg(v2 + (size_t)i * PLANE + (size_t)gb1 * M + m);
                vs0[i] = __ldg(v1 + (size_t)i * PLANE + (size_t)gb0 * M + m);
                vs1[i] = __ldg(v1 + (size_t)i * PLANE + (size_t)gb1 * M + m);
            }
#pragma unroll
            for (int i = 0; i < 3; ++i)
#pragma unroll
                for (int nt = 0; nt < 4; ++nt) {
                    dv[i][nt][0] += sv0[i] * Tsv[nt][0] + vs0[i] * Tvs[nt][0];
                    dv[i][nt][1] += sv0[i] * Tsv[nt][1] + vs0[i] * Tvs[nt][1];
                    dv[i][nt][2] += sv1[i] * Tsv[nt][2] + vs1[i] * Tvs[nt][2];
                    dv[i][nt][3] += sv1[i] * Tsv[nt][3] + vs1[i] * Tvs[nt][3];
                }
#pragma unroll
            for (int nt = 0; nt < 4; ++nt)
#pragma unroll
                for (int j2 = 0; j2 < 4; ++j2) { Tsv[nt][j2] = 0.f; Tvs[nt][j2] = 0.f; }
            ++m; c = 0;
        } else ++c;
        __syncthreads();
    }

#pragma unroll
    for (int i = 0; i < 3; ++i) {
        float* op = tv + (size_t)i * PLANE;
#pragma unroll
        for (int nt = 0; nt < 4; ++nt) {
            const int col = ng * 32 + nt * 8 + 2 * t4;
            *(float2*)(op + (size_t)gb0 * 128 + col) = make_float2(cscale * dv[i][nt][0], cscale * dv[i][nt][1]);
            *(float2*)(op + (size_t)gb1 * 128 + col) = make_float2(cscale * dv[i][nt][2], cscale * dv[i][nt][3]);
        }
    }
}

// ============ merged linear GEMM (pointer-table, grid.y = role) ============
struct LinPtrs {
    const float* X[8];
    const float* Wt[8];
    float* Y[8];
};
template <int NC>
__global__ __launch_bounds__(256)
void lin_kernel(LinPtrs p, int K, float scale) {
    constexpr int N = 32 * NC;
    const float* X  = p.X[blockIdx.y];
    const float* Wm = p.Wt[blockIdx.y];
    float* Y        = p.Y[blockIdx.y];
    __shared__ float Xs[32][33];
    __shared__ float Ws[32][N + 1];
    const int tx = threadIdx.x, ty = threadIdx.y;
    const int tid = ty * 32 + tx;
    const int row0 = blockIdx.x * 32;
    float acc[4][NC];
#pragma unroll
    for (int r = 0; r < 4; ++r)
#pragma unroll
        for (int j = 0; j < NC; ++j) acc[r][j] = 0.f;
    for (int k0 = 0; k0 < K; k0 += 32) {
#pragma unroll
        for (int e = tid; e < 32 * 32; e += 256) {
            int r = e >> 5, kk = e & 31;
            Xs[r][kk] = X[(size_t)(row0 + r) * K + k0 + kk];
        }
        for (int e = tid; e < 32 * N; e += 256) {
            int kk = e / N, n = e - kk * N;
            Ws[kk][n] = Wm[(size_t)(k0 + kk) * N + n];
        }
        __syncthreads();
#pragma unroll 8
        for (int kk = 0; kk < 32; ++kk) {
            float wvv[NC];
#pragma unroll
            for (int j = 0; j < NC; ++j) wvv[j] = Ws[kk][tx * NC + j];
#pragma unroll
            for (int r = 0; r < 4; ++r) {
                float xv = Xs[ty * 4 + r][kk];
#pragma unroll
                for (int j = 0; j < NC; ++j) acc[r][j] += xv * wvv[j];
            }
        }
        __syncthreads();
    }
#pragma unroll
    for (int r = 0; r < 4; ++r)
#pragma unroll
        for (int j = 0; j < NC; ++j)
            Y[(size_t)(row0 + ty * 4 + r) * N + tx * NC + j] = scale * acc[r][j];
}

// ============ split / pack / gate ============
__global__ void split_kernel(const float* __restrict__ x,
                             float* __restrict__ s, float* __restrict__ v) {
    int i = blockIdx.x * 256 + threadIdx.x;
    if (i >= BATCH * 64) return;
    int b = i >> 6, u = i & 63;
    const float* xr = x + b * 256;
    s[i] = xr[u];
    v[0 * PLANE + i] = xr[64 + 3 * u + 0];
    v[1 * PLANE + i] = xr[64 + 3 * u + 1];
    v[2 * PLANE + i] = xr[64 + 3 * u + 2];
}
__global__ void pack_kernel(const float* __restrict__ s,
                            const float* __restrict__ v, float* __restrict__ out) {
    int i = blockIdx.x * 256 + threadIdx.x;
    if (i >= BATCH * 64) return;
    int b = i >> 6, u = i & 63;
    float* orow = out + b * 256;
    orow[u] = s[i];
    orow[64 + 3 * u + 0] = v[0 * PLANE + i];
    orow[64 + 3 * u + 1] = v[1 * PLANE + i];
    orow[64 + 3 * u + 2] = v[2 * PLANE + i];
}
__global__ void gate_kernel(const float* __restrict__ sl, const float* __restrict__ g,
                            const float* __restrict__ vl,
                            float* __restrict__ gs, float* __restrict__ gv) {
    int i = blockIdx.x * 256 + threadIdx.x;
    if (i >= BATCH * 128) return;
    gs[i] = GAIN * tanhf(sl[i]);
    float t = GAIN * tanhf(g[i]);
    gv[0 * PLANE + i] = t * vl[0 * PLANE + i];
    gv[1 * PLANE + i] = t * vl[1 * PLANE + i];
    gv[2 * PLANE + i] = t * vl[2 * PLANE + i];
}

extern "C" void kernel_launch(void* const* d_in, const int* in_sizes, int n_in,
                              void* d_out, int out_size) {
    const float* in[29];
    for (int i = 0; i < 29; ++i) in[i] = (const float*)d_in[i];
    float* out = (float*)d_out;

    float *s, *v, *s1, *v1, *s2, *v2, *ts, *tv;
    uint32_t *wp1, *wp2, *wv1, *wv2;
    cudaGetSymbolAddress((void**)&s,  g_s);
    cudaGetSymbolAddress((void**)&v,  g_v);
    cudaGetSymbolAddress((void**)&s1, g_s1);
    cudaGetSymbolAddress((void**)&v1, g_v1);
    cudaGetSymbolAddress((void**)&s2, g_s2);
    cudaGetSymbolAddress((void**)&v2, g_v2);
    cudaGetSymbolAddress((void**)&ts, g_ts);
    cudaGetSymbolAddress((void**)&tv, g_tv);
    cudaGetSymbolAddress((void**)&wp1, g_wp1);
    cudaGetSymbolAddress((void**)&wp2, g_wp2);
    cudaGetSymbolAddress((void**)&wv1, g_wv1);
    cudaGetSymbolAddress((void**)&wv2, g_wv2);

    const int P_SMEM  = 4 * 4224 * 4;                       // 67584
    const int V_SMEM1 = (16896 + 4096) * 4;                 // 83968
    const int V_SMEM2 = (16896 + 8192) * 4;                 // 100352
    cudaFuncSetAttribute(tp_p_kernel<64>,  cudaFuncAttributeMaxDynamicSharedMemorySize, P_SMEM);
    cudaFuncSetAttribute(tp_p_kernel<128>, cudaFuncAttributeMaxDynamicSharedMemorySize, P_SMEM);
    cudaFuncSetAttribute(tp_v_kernel<64>,  cudaFuncAttributeMaxDynamicSharedMemorySize, V_SMEM1);
    cudaFuncSetAttribute(tp_v_kernel<128>, cudaFuncAttributeMaxDynamicSharedMemorySize, V_SMEM2);

    const float c64  = 0.125f;
    const float c128 = 0.08838834764831845f;
    const float ctp1 = 1.0f / (64.0f  * 1.4142135623730951f);
    const float ctp2 = 1.0f / (128.0f * 1.4142135623730951f);

    // prepass
    {
        const int t1 = (64 * 64 / 2) * 128, t2 = (128 * 128 / 2) * 128;
        const int p1 = 64 * 64 * 128, p2 = 128 * 128 * 128;
        pack_weights_kernel<<<(t1 + 255) / 256, 256>>>(in[5], wp1, 64);
        pack_weights_kernel<<<(t1 + 255) / 256, 256>>>(in[6], wp1 + p1, 64);
        pack_weights_v_kernel<<<(t1 + 255) / 256, 256>>>(in[7], wv1, 64, 1);
        pack_weights_v_kernel<<<(t1 + 255) / 256, 256>>>(in[8], wv1 + p1, 64, 0);
        pack_weights_kernel<<<(t2 + 255) / 256, 256>>>(in[18], wp2, 128);
        pack_weights_kernel<<<(t2 + 255) / 256, 256>>>(in[19], wp2 + p2, 128);
        pack_weights_v_kernel<<<(t2 + 255) / 256, 256>>>(in[20], wv2, 128, 1);
        pack_weights_v_kernel<<<(t2 + 255) / 256, 256>>>(in[21], wv2 + p2, 128, 0);
    }

    split_kernel<<<BATCH * 64 / 256, 256>>>(in[0], s, v);

    dim3 lblk(32, 8);
    const int GX = BATCH / 32;

    for (int blk = 0; blk < 2; ++blk) {
        const int M = blk ? 128 : 64;
        const float clin = blk ? c128 : c64;
        const float ctp  = blk ? ctp2 : ctp1;
        const int wo = blk ? 13 : 0;   // weight index offset

        // lin1+lin2 (8 roles)
        LinPtrs a{};
        a.X[0] = s;  a.Wt[0] = in[wo + 1]; a.Y[0] = s1;
        for (int i = 0; i < 3; ++i) { a.X[1+i] = v + (size_t)i * PLANE; a.Wt[1+i] = in[wo + 2]; a.Y[1+i] = v1 + (size_t)i * PLANE; }
        a.X[4] = s;  a.Wt[4] = in[wo + 3]; a.Y[4] = s2;
        for (int i = 0; i < 3; ++i) { a.X[5+i] = v + (size_t)i * PLANE; a.Wt[5+i] = in[wo + 4]; a.Y[5+i] = v2 + (size_t)i * PLANE; }
        if (blk) lin_kernel<4><<<dim3(GX, 8), lblk>>>(a, 128, clin);
        else     lin_kernel<2><<<dim3(GX, 8), lblk>>>(a, 64,  clin);

        if (blk) {
            tp_p_kernel<128><<<GX, 256, P_SMEM>>>(s1, v1, s2, v2, wp2, ts, ctp);
            tp_v_kernel<128><<<GX, 256, V_SMEM2>>>(s1, v1, s2, v2, wv2, tv, ctp);
        } else {
            tp_p_kernel<64><<<GX, 256, P_SMEM>>>(s1, v1, s2, v2, wp1, ts, ctp);
            tp_v_kernel<64><<<GX, 256, V_SMEM1>>>(s1, v1, s2, v2, wv1, tv, ctp);
        }

        // gate-pre (5 roles): sl, g, vl x3
        LinPtrs gp{};
        gp.X[0] = ts; gp.Wt[0] = in[wo + 9];  gp.Y[0] = s1;
        gp.X[1] = ts; gp.Wt[1] = in[wo + 10]; gp.Y[1] = s2;
        for (int i = 0; i < 3; ++i) { gp.X[2+i] = tv + (size_t)i * PLANE; gp.Wt[2+i] = in[wo + 11]; gp.Y[2+i] = v1 + (size_t)i * PLANE; }
        lin_kernel<4><<<dim3(GX, 5), lblk>>>(gp, 128, c128);

        gate_kernel<<<BATCH * 128 / 256, 256>>>(s1, s2, v1, ts, tv);

        // out-lin (4 roles)
        LinPtrs ol{};
        ol.X[0] = ts; ol.Wt[0] = in[wo + 12]; ol.Y[0] = s;
        for (int i = 0; i < 3; ++i) { ol.X[1+i] = tv + (size_t)i * PLANE; ol.Wt[1+i] = in[wo + 13]; ol.Y[1+i] = v + (size_t)i * PLANE; }
        lin_kernel<4><<<dim3(GX, 4), lblk>>>(ol, 128, c128);
    }

    // final linear (4 roles, N=64)
    LinPtrs f{};
    f.X[0] = s; f.Wt[0] = in[27]; f.Y[0] = s1;
    for (int i = 0; i < 3; ++i) { f.X[1+i] = v + (size_t)i * PLANE; f.Wt[1+i] = in[28]; f.Y[1+i] = v1 + (size_t)i * PLANE; }
    lin_kernel<2><<<dim3(GX, 4), lblk>>>(f, 128, c128);

    pack_kernel<<<BATCH * 64 / 256, 256>>>(s1, v1, out);
}